// round 1
// baseline (speedup 1.0000x reference)
#include <cuda_runtime.h>
#include <math.h>

// Problem constants
#define NTOK 4096          // B*T = 2*2048
#define CDIM 1024          // n_embed
#define NEXP 8
#define DFF  4096
#define CAP  1024          // NTOK*2/8
#define NHEADS 16
#define HD   64
#define TSEQ 2048
#define BSZ  2

// ---------------- scratch (device globals; no allocations) ----------------
__device__ float g_h1   [NTOK * CDIM];
__device__ float g_qkv  [NTOK * 3 * CDIM];
__device__ float g_attn [NTOK * CDIM];     // permuted pre-projection activation
__device__ float g_x2   [NTOK * CDIM];     // x + attn_proj
__device__ float g_h2   [NTOK * CDIM];     // ln2(x2)
__device__ float g_logits [NTOK * NEXP];
__device__ float g_nlogits[NTOK * NEXP];
__device__ int   g_sel  [NTOK];            // e0 | (e1<<8)
__device__ float g_gate [NTOK * 2];
__device__ int   g_slot_idx [NEXP * CAP];
__device__ float g_slot_gate[NEXP * CAP];
__device__ float g_xe  [NEXP * CAP * CDIM];
__device__ float g_hid [(size_t)NEXP * CAP * DFF];
__device__ float g_upd [NTOK * CDIM];
__device__ float g_ent;

// ---------------- zero scratch ----------------
__global__ void zero_kernel() {
    size_t i = (size_t)blockIdx.x * blockDim.x + threadIdx.x;
    ((float4*)g_upd)[i] = make_float4(0.f, 0.f, 0.f, 0.f);
    if (i == 0) g_ent = 0.f;
}

// ---------------- layernorm (1 block per row, 256 threads) ----------------
__global__ __launch_bounds__(256) void ln_kernel(const float* __restrict__ x,
                                                 const float* __restrict__ gam,
                                                 const float* __restrict__ bet,
                                                 float* __restrict__ out) {
    __shared__ float red[8];
    __shared__ float s_mu, s_rs;
    int row = blockIdx.x, tid = threadIdx.x;
    const float* xr = x + (size_t)row * CDIM;
    float v[4];
    float s = 0.f;
#pragma unroll
    for (int i = 0; i < 4; i++) { v[i] = xr[tid + i * 256]; s += v[i]; }
    for (int o = 16; o; o >>= 1) s += __shfl_xor_sync(~0u, s, o);
    if ((tid & 31) == 0) red[tid >> 5] = s;
    __syncthreads();
    if (tid < 8) {
        float t = red[tid];
        for (int o = 4; o; o >>= 1) t += __shfl_xor_sync(0xffu, t, o);
        if (tid == 0) s_mu = t * (1.f / CDIM);
    }
    __syncthreads();
    float mu = s_mu;
    float s2 = 0.f;
#pragma unroll
    for (int i = 0; i < 4; i++) { float d = v[i] - mu; s2 += d * d; }
    for (int o = 16; o; o >>= 1) s2 += __shfl_xor_sync(~0u, s2, o);
    if ((tid & 31) == 0) red[tid >> 5] = s2;
    __syncthreads();
    if (tid < 8) {
        float t = red[tid];
        for (int o = 4; o; o >>= 1) t += __shfl_xor_sync(0xffu, t, o);
        if (tid == 0) s_rs = rsqrtf(t * (1.f / CDIM) + 1e-5f);
    }
    __syncthreads();
    float rs = s_rs;
    float* orow = out + (size_t)row * CDIM;
#pragma unroll
    for (int i = 0; i < 4; i++) {
        int c = tid + i * 256;
        orow[c] = (v[i] - mu) * rs * gam[c] + bet[c];
    }
}

// ---------------- generic tiled SGEMM 128x128x8, 8x8 micro-tile ----------------
// EPI: 0 = store (+bias), 1 = store relu(+bias), 2 = store + residual,
//      3 = gated atomic scatter into scat[] using slot tables (bias added first)
template <int EPI>
__global__ __launch_bounds__(256) void sgemm_kernel(
    const float* __restrict__ A, const float* __restrict__ B, float* __restrict__ Cout,
    int M, int N, int K,
    const float* __restrict__ bias, const float* __restrict__ res,
    const int* __restrict__ sidx, const float* __restrict__ sgate,
    float* __restrict__ scat,
    size_t sA, size_t sB, size_t sC, int sBias)
{
    __shared__ float As[8][128];
    __shared__ float Bs[8][128];
    int z = blockIdx.z;
    A += (size_t)z * sA;
    B += (size_t)z * sB;
    if (Cout) Cout += (size_t)z * sC;
    if (bias) bias += (size_t)z * sBias;

    int tid = threadIdx.x;
    int arow = tid >> 1, acol = (tid & 1) << 2;
    int brow = tid >> 5, bcol = (tid & 31) << 2;
    const float* Ap = A + (size_t)(blockIdx.y * 128 + arow) * K + acol;
    const float* Bp = B + (size_t)brow * N + blockIdx.x * 128 + bcol;

    float acc[8][8];
#pragma unroll
    for (int i = 0; i < 8; i++)
#pragma unroll
        for (int j = 0; j < 8; j++) acc[i][j] = 0.f;

    int ty = tid >> 4, tx = tid & 15;
    for (int k0 = 0; k0 < K; k0 += 8) {
        float4 av = *(const float4*)Ap; Ap += 8;
        float4 bv = *(const float4*)Bp; Bp += (size_t)8 * N;
        As[acol + 0][arow] = av.x; As[acol + 1][arow] = av.y;
        As[acol + 2][arow] = av.z; As[acol + 3][arow] = av.w;
        *(float4*)&Bs[brow][bcol] = bv;
        __syncthreads();
#pragma unroll
        for (int k = 0; k < 8; k++) {
            float af[8], bf[8];
#pragma unroll
            for (int i = 0; i < 8; i++) af[i] = As[k][ty * 8 + i];
#pragma unroll
            for (int j = 0; j < 8; j++) bf[j] = Bs[k][tx * 8 + j];
#pragma unroll
            for (int i = 0; i < 8; i++)
#pragma unroll
                for (int j = 0; j < 8; j++) acc[i][j] += af[i] * bf[j];
        }
        __syncthreads();
    }

    int rbase = blockIdx.y * 128 + ty * 8;
    int cbase = blockIdx.x * 128 + tx * 8;
#pragma unroll
    for (int i = 0; i < 8; i++) {
        int row = rbase + i;
#pragma unroll
        for (int j = 0; j < 8; j++) {
            int col = cbase + j;
            float v = acc[i][j];
            if (bias) v += bias[col];
            if (EPI == 1) v = fmaxf(v, 0.f);
            if (EPI == 2) v += res[(size_t)row * N + col];
            if (EPI == 3) {
                int gs = z * M + row;
                int idx = sidx[gs];
                if (idx >= 0)
                    atomicAdd(&scat[(size_t)idx * N + col], sgate[gs] * v);
            } else {
                Cout[(size_t)row * N + col] = v;
            }
        }
    }
}

// ---------------- attention (flash-style, 1 warp per query row) ----------------
__global__ __launch_bounds__(256, 1) void attn_kernel(const float* __restrict__ qkv,
                                                      float* __restrict__ aout) {
    __shared__ float Ks[64][65];
    __shared__ float Vs[64][65];
    int bh = blockIdx.y;
    int b = bh >> 4, h = bh & 15;
    int warp = threadIdx.x >> 5, lane = threadIdx.x & 31;
    int t = blockIdx.x * 8 + warp;

    const float* qp = qkv + ((size_t)(b * TSEQ + t)) * 3072 + h * 64;
    float q[64];
#pragma unroll
    for (int d = 0; d < 64; d++) q[d] = qp[d];

    float m = -1e30f, l = 0.f;
    float acc[64];
#pragma unroll
    for (int d = 0; d < 64; d++) acc[d] = 0.f;

    const float* kbase = qkv + (size_t)b * TSEQ * 3072 + 1024 + h * 64;
    const float* vbase = kbase + 1024;

    for (int s0 = 0; s0 < TSEQ; s0 += 64) {
        __syncthreads();
        for (int i = threadIdx.x; i < 64 * 16; i += 256) {
            int j = i >> 4, dv = (i & 15) << 2;
            float4 kv = *(const float4*)(kbase + (size_t)(s0 + j) * 3072 + dv);
            float4 vv = *(const float4*)(vbase + (size_t)(s0 + j) * 3072 + dv);
            Ks[j][dv] = kv.x; Ks[j][dv + 1] = kv.y; Ks[j][dv + 2] = kv.z; Ks[j][dv + 3] = kv.w;
            Vs[j][dv] = vv.x; Vs[j][dv + 1] = vv.y; Vs[j][dv + 2] = vv.z; Vs[j][dv + 3] = vv.w;
        }
        __syncthreads();
#pragma unroll
        for (int jj = 0; jj < 2; jj++) {
            int j = lane + (jj << 5);
            float sc = 0.f;
#pragma unroll
            for (int d = 0; d < 64; d++) sc += q[d] * Ks[j][d];
            sc *= 0.125f;
            if (sc > m) {
                float r = __expf(m - sc);
                l = l * r + 1.f;
#pragma unroll
                for (int d = 0; d < 64; d++) acc[d] = acc[d] * r + Vs[j][d];
                m = sc;
            } else {
                float pp = __expf(sc - m);
                l += pp;
#pragma unroll
                for (int d = 0; d < 64; d++) acc[d] += pp * Vs[j][d];
            }
        }
    }
    // merge per-lane partial softmaxes
    float M = m;
    for (int o = 16; o; o >>= 1) M = fmaxf(M, __shfl_xor_sync(~0u, M, o));
    float f = __expf(m - M);
    float lf = l * f;
    for (int o = 16; o; o >>= 1) lf += __shfl_xor_sync(~0u, lf, o);
    float invL = 1.f / lf;

    // write through the reference's transpose/reshape permutation
    float* ab = aout + (size_t)b * TSEQ * CDIM;
    int fbase = h * 131072 + t * 64;
#pragma unroll
    for (int d = 0; d < 64; d++) {
        float vs = acc[d] * f;
        for (int o = 16; o; o >>= 1) vs += __shfl_xor_sync(~0u, vs, o);
        if (lane == (d & 31)) {
            int fi = fbase + d;
            ab[(size_t)(fi & 2047) * CDIM + (fi >> 11)] = vs * invL;
        }
    }
}

// ---------------- routing GEMV (warp per token) ----------------
__global__ __launch_bounds__(256) void route_kernel(const float* __restrict__ wr,
                                                    const float* __restrict__ br,
                                                    const float* __restrict__ wn,
                                                    const float* __restrict__ bn) {
    int warp = threadIdx.x >> 5, lane = threadIdx.x & 31;
    int n = blockIdx.x * 8 + warp;
    const float* hp = g_h2 + (size_t)n * CDIM;
    float pr[8], pn[8];
#pragma unroll
    for (int e = 0; e < 8; e++) { pr[e] = 0.f; pn[e] = 0.f; }
    for (int c = lane; c < CDIM; c += 32) {
        float hv = hp[c];
#pragma unroll
        for (int e = 0; e < 8; e++) {
            pr[e] += hv * wr[c * 8 + e];
            pn[e] += hv * wn[c * 8 + e];
        }
    }
#pragma unroll
    for (int e = 0; e < 8; e++) {
        for (int o = 16; o; o >>= 1) {
            pr[e] += __shfl_xor_sync(~0u, pr[e], o);
            pn[e] += __shfl_xor_sync(~0u, pn[e], o);
        }
    }
    if (lane == 0) {
#pragma unroll
        for (int e = 0; e < 8; e++) {
            g_logits[n * 8 + e]  = pr[e] + br[e];
            g_nlogits[n * 8 + e] = pn[e] + bn[e];
        }
    }
}

// ---------------- per-token routing epilogue + entropy ----------------
__global__ __launch_bounds__(256) void route_post_kernel(const float* __restrict__ noise) {
    __shared__ float red[8];
    int n = blockIdx.x * blockDim.x + threadIdx.x;
    float noisy[8];
    float mx = -1e30f;
#pragma unroll
    for (int e = 0; e < 8; e++) {
        float nl = g_nlogits[n * 8 + e];
        float sp = log1pf(expf(-fabsf(nl))) + fmaxf(nl, 0.f);   // softplus
        float v = g_logits[n * 8 + e] + noise[n * 8 + e] * sp;
        noisy[e] = v;
        mx = fmaxf(mx, v);
    }
    float s = 0.f, p[8];
#pragma unroll
    for (int e = 0; e < 8; e++) { p[e] = expf(noisy[e] - mx); s += p[e]; }
    float inv = 1.f / s, ent = 0.f;
#pragma unroll
    for (int e = 0; e < 8; e++) { float pe = p[e] * inv; ent -= pe * logf(pe + 1e-8f); }

    int i0 = 0;
#pragma unroll
    for (int e = 1; e < 8; e++) if (noisy[e] > noisy[i0]) i0 = e;
    int i1 = (i0 == 0) ? 1 : 0;
#pragma unroll
    for (int e = 0; e < 8; e++) if (e != i0 && noisy[e] > noisy[i1]) i1 = e;
    float dgl = expf(noisy[i1] - noisy[i0]);
    float g0 = 1.f / (1.f + dgl);
    float g1 = dgl * g0;
    g_sel[n] = i0 | (i1 << 8);
    g_gate[2 * n] = g0;
    g_gate[2 * n + 1] = g1;

    // entropy block reduce -> atomic
    float es = ent;
    for (int o = 16; o; o >>= 1) es += __shfl_xor_sync(~0u, es, o);
    int lane = threadIdx.x & 31, wid = threadIdx.x >> 5;
    if (lane == 0) red[wid] = es;
    __syncthreads();
    if (threadIdx.x < 8) {
        float t = red[threadIdx.x];
        for (int o = 4; o; o >>= 1) t += __shfl_xor_sync(0xffu, t, o);
        if (threadIdx.x == 0) atomicAdd(&g_ent, t);
    }
}

// ---------------- ordered capacity assignment (1 warp, ballot scan) ----------------
__global__ void assign_kernel() {
    int lane = threadIdx.x;
    int cnt[8];
#pragma unroll
    for (int e = 0; e < 8; e++) cnt[e] = 0;
    unsigned lt = (1u << lane) - 1u;
    for (int n0 = 0; n0 < NTOK; n0 += 32) {
        int n = n0 + lane;
        int sel = g_sel[n];
        int e0 = sel & 255, e1 = (sel >> 8) & 255;
        float g0 = g_gate[2 * n], g1 = g_gate[2 * n + 1];
#pragma unroll
        for (int e = 0; e < 8; e++) {
            bool mt = (e0 == e) || (e1 == e);
            unsigned mask = __ballot_sync(~0u, mt);
            if (mt) {
                int r = cnt[e] + __popc(mask & lt);
                if (r < CAP) {
                    g_slot_idx[e * CAP + r]  = n;
                    g_slot_gate[e * CAP + r] = (e0 == e) ? g0 : g1;
                }
            }
            cnt[e] += __popc(mask);
        }
    }
#pragma unroll
    for (int e = 0; e < 8; e++) {
        for (int r = cnt[e] + lane; r < CAP; r += 32) {
            g_slot_idx[e * CAP + r]  = -1;
            g_slot_gate[e * CAP + r] = 0.f;
        }
    }
}

// ---------------- gather tokens into expert buffers ----------------
__global__ __launch_bounds__(256) void gather_kernel() {
    int s = blockIdx.x;
    int idx = g_slot_idx[s];
    float4* dst = (float4*)(g_xe + (size_t)s * CDIM);
    int t = threadIdx.x;
    if (idx >= 0) {
        const float4* src = (const float4*)(g_h2 + (size_t)idx * CDIM);
        dst[t] = src[t];
    } else {
        dst[t] = make_float4(0.f, 0.f, 0.f, 0.f);
    }
}

// ---------------- final: out = x2 + updates ; tail = entropy/N ----------------
__global__ void final_kernel(float* __restrict__ out, int out_size) {
    int i = blockIdx.x * blockDim.x + threadIdx.x;
    if (i < NTOK * CDIM) out[i] = g_x2[i] + g_upd[i];
    else if (i < out_size) out[i] = g_ent * (1.f / NTOK);
}

// ---------------- host launcher ----------------
static float* symf(const void* s) { void* p = nullptr; cudaGetSymbolAddress(&p, s); return (float*)p; }
static int*   symi(const void* s) { void* p = nullptr; cudaGetSymbolAddress(&p, s); return (int*)p; }

extern "C" void kernel_launch(void* const* d_in, const int* in_sizes, int n_in,
                              void* d_out, int out_size) {
    const float* x       = (const float*)d_in[0];
    const float* noise   = (const float*)d_in[1];
    const float* gamma1  = (const float*)d_in[2];
    const float* beta1   = (const float*)d_in[3];
    const float* gamma2  = (const float*)d_in[4];
    const float* beta2   = (const float*)d_in[5];
    const float* w_qkv   = (const float*)d_in[6];
    const float* w_out   = (const float*)d_in[7];
    const float* w_route = (const float*)d_in[8];
    const float* b_route = (const float*)d_in[9];
    const float* w_noise = (const float*)d_in[10];
    const float* b_noise = (const float*)d_in[11];
    const float* w1      = (const float*)d_in[12];
    const float* b1      = (const float*)d_in[13];
    const float* w2      = (const float*)d_in[14];
    const float* b2      = (const float*)d_in[15];
    float* out = (float*)d_out;

    float* p_h1   = symf(g_h1);
    float* p_qkv  = symf(g_qkv);
    float* p_attn = symf(g_attn);
    float* p_x2   = symf(g_x2);
    float* p_h2   = symf(g_h2);
    float* p_xe   = symf(g_xe);
    float* p_hid  = symf(g_hid);
    float* p_upd  = symf(g_upd);
    int*   p_sidx = symi(g_slot_idx);
    float* p_sg   = symf(g_slot_gate);

    // 0) zero updates + entropy
    zero_kernel<<<NTOK * CDIM / 4 / 256, 256>>>();
    // 1) ln1
    ln_kernel<<<NTOK, 256>>>(x, gamma1, beta1, p_h1);
    // 2) qkv = h1 @ w_qkv  [4096 x 3072 x 1024]
    sgemm_kernel<0><<<dim3(3072 / 128, 4096 / 128, 1), 256>>>(
        p_h1, w_qkv, p_qkv, 4096, 3072, 1024,
        nullptr, nullptr, nullptr, nullptr, nullptr, 0, 0, 0, 0);
    // 3) attention -> permuted activation
    attn_kernel<<<dim3(TSEQ / 8, BSZ * NHEADS), 256>>>(p_qkv, p_attn);
    // 4) x2 = x + attn @ w_out  [4096 x 1024 x 1024]
    sgemm_kernel<2><<<dim3(1024 / 128, 4096 / 128, 1), 256>>>(
        p_attn, w_out, p_x2, 4096, 1024, 1024,
        nullptr, x, nullptr, nullptr, nullptr, 0, 0, 0, 0);
    // 5) ln2
    ln_kernel<<<NTOK, 256>>>(p_x2, gamma2, beta2, p_h2);
    // 6) routing GEMV
    route_kernel<<<NTOK / 8, 256>>>(w_route, b_route, w_noise, b_noise);
    // 7) routing epilogue (noisy top-2, gates, entropy)
    route_post_kernel<<<NTOK / 256, 256>>>(noise);
    // 8) ordered capacity assignment
    assign_kernel<<<1, 32>>>();
    // 9) gather expert inputs
    gather_kernel<<<NEXP * CAP, 256>>>();
    // 10) hid = relu(xe @ w1 + b1)  per expert [1024 x 4096 x 1024]
    sgemm_kernel<1><<<dim3(4096 / 128, 1024 / 128, NEXP), 256>>>(
        p_xe, w1, p_hid, 1024, 4096, 1024,
        b1, nullptr, nullptr, nullptr, nullptr,
        (size_t)CAP * CDIM, (size_t)CDIM * DFF, (size_t)CAP * DFF, DFF);
    // 11) yo = hid @ w2 + b2, gated atomic scatter into updates [1024 x 1024 x 4096]
    sgemm_kernel<3><<<dim3(1024 / 128, 1024 / 128, NEXP), 256>>>(
        p_hid, w2, nullptr, 1024, 1024, 4096,
        b2, nullptr, p_sidx, p_sg, p_upd,
        (size_t)CAP * DFF, (size_t)DFF * CDIM, 0, CDIM);
    // 12) final add + entropy tail
    final_kernel<<<(out_size + 255) / 256, 256>>>(out, out_size);
}

// round 2
// speedup vs baseline: 1.4123x; 1.4123x over previous
#include <cuda_runtime.h>
#include <math.h>
#include <stdint.h>

// Problem constants
#define NTOK 4096          // B*T = 2*2048
#define CDIM 1024          // n_embed
#define NEXP 8
#define DFF  4096
#define CAP  1024          // NTOK*2/8
#define NHEADS 16
#define HD   64
#define TSEQ 2048
#define BSZ  2

// ---------------- scratch (device globals; no allocations) ----------------
__device__ float g_h1   [NTOK * CDIM];
__device__ float g_qkv  [NTOK * 3 * CDIM];
__device__ float g_attn [NTOK * CDIM];     // permuted pre-projection activation
__device__ float g_x2   [NTOK * CDIM];     // x + attn_proj
__device__ float g_h2   [NTOK * CDIM];     // ln2(x2)
__device__ float g_logits [NTOK * NEXP];
__device__ float g_nlogits[NTOK * NEXP];
__device__ int   g_sel  [NTOK];            // e0 | (e1<<8)
__device__ float g_gate [NTOK * 2];
__device__ int   g_slot_idx [NEXP * CAP];
__device__ float g_slot_gate[NEXP * CAP];
__device__ float g_xe  [NEXP * CAP * CDIM];
__device__ float g_hid [(size_t)NEXP * CAP * DFF];
__device__ float g_upd [NTOK * CDIM];
__device__ float g_ent;

// ---------------- helpers ----------------
__device__ __forceinline__ float ftf(float x) {
    float r;
    asm("cvt.rna.tf32.f32 %0, %1;" : "=f"(r) : "f"(x));
    return r;
}

__device__ __forceinline__ void mma_tf32(float c[4], const uint32_t a[4], const uint32_t b[2]) {
    asm volatile(
        "mma.sync.aligned.m16n8k8.row.col.f32.tf32.tf32.f32 "
        "{%0,%1,%2,%3},{%4,%5,%6,%7},{%8,%9},{%0,%1,%2,%3};"
        : "+f"(c[0]), "+f"(c[1]), "+f"(c[2]), "+f"(c[3])
        : "r"(a[0]), "r"(a[1]), "r"(a[2]), "r"(a[3]), "r"(b[0]), "r"(b[1]));
}

// ---------------- zero scratch ----------------
__global__ void zero_kernel() {
    size_t i = (size_t)blockIdx.x * blockDim.x + threadIdx.x;
    ((float4*)g_upd)[i] = make_float4(0.f, 0.f, 0.f, 0.f);
    if (i == 0) g_ent = 0.f;
}

// ---------------- layernorm (1 block per row, 256 threads) ----------------
__global__ __launch_bounds__(256) void ln_kernel(const float* __restrict__ x,
                                                 const float* __restrict__ gam,
                                                 const float* __restrict__ bet,
                                                 float* __restrict__ out) {
    __shared__ float red[8];
    __shared__ float s_mu, s_rs;
    int row = blockIdx.x, tid = threadIdx.x;
    const float* xr = x + (size_t)row * CDIM;
    float v[4];
    float s = 0.f;
#pragma unroll
    for (int i = 0; i < 4; i++) { v[i] = xr[tid + i * 256]; s += v[i]; }
    for (int o = 16; o; o >>= 1) s += __shfl_xor_sync(~0u, s, o);
    if ((tid & 31) == 0) red[tid >> 5] = s;
    __syncthreads();
    if (tid < 8) {
        float t = red[tid];
        for (int o = 4; o; o >>= 1) t += __shfl_xor_sync(0xffu, t, o);
        if (tid == 0) s_mu = t * (1.f / CDIM);
    }
    __syncthreads();
    float mu = s_mu;
    float s2 = 0.f;
#pragma unroll
    for (int i = 0; i < 4; i++) { float d = v[i] - mu; s2 += d * d; }
    for (int o = 16; o; o >>= 1) s2 += __shfl_xor_sync(~0u, s2, o);
    if ((tid & 31) == 0) red[tid >> 5] = s2;
    __syncthreads();
    if (tid < 8) {
        float t = red[tid];
        for (int o = 4; o; o >>= 1) t += __shfl_xor_sync(0xffu, t, o);
        if (tid == 0) s_rs = rsqrtf(t * (1.f / CDIM) + 1e-5f);
    }
    __syncthreads();
    float rs = s_rs;
    float* orow = out + (size_t)row * CDIM;
#pragma unroll
    for (int i = 0; i < 4; i++) {
        int c = tid + i * 256;
        orow[c] = (v[i] - mu) * rs * gam[c] + bet[c];
    }
}

// ---------------- tf32 tensor-core GEMM 128x128x16, double-buffered ----------------
// EPI: 0 = store (+bias), 1 = store relu(+bias), 2 = store + residual,
//      3 = gated atomic scatter into scat[] using slot tables (bias added first)
template <int EPI>
__global__ __launch_bounds__(256) void tgemm_kernel(
    const float* __restrict__ A, const float* __restrict__ B, float* __restrict__ Cout,
    int M, int N, int K,
    const float* __restrict__ bias, const float* __restrict__ res,
    const int* __restrict__ sidx, const float* __restrict__ sgate,
    float* __restrict__ scat,
    size_t sA, size_t sB, size_t sC, int sBias)
{
    __shared__ float As[2][16][132];   // [k][m], padded
    __shared__ float Bs[2][16][132];   // [k][n], padded

    const int z = blockIdx.z;
    A += (size_t)z * sA;
    B += (size_t)z * sB;
    if (Cout) Cout += (size_t)z * sC;
    if (bias) bias += (size_t)z * sBias;

    const int tid  = threadIdx.x;
    const int lane = tid & 31, wid = tid >> 5;
    const int wr = wid >> 2, wc = wid & 3;      // warp tile: 64(M) x 32(N)
    const int tg = lane >> 2, tq = lane & 3;

    // A staging: m = tid%128, k base = (tid/128)*8 (two float4)
    const int am  = tid & 127;
    const int akb = (tid >> 7) << 3;
    const float* Ap = A + (size_t)(blockIdx.y * 128 + am) * K + akb;
    // B staging: kb = tid/32 (rows kb, kb+8), col4 = (lane)*4
    const int bkb = tid >> 5;
    const int bc4 = (tid & 31) << 2;
    const float* Bp = B + (size_t)bkb * N + blockIdx.x * 128 + bc4;

    float4 ra0, ra1, rb0, rb1;
    ra0 = *(const float4*)(Ap);
    ra1 = *(const float4*)(Ap + 4);
    rb0 = *(const float4*)(Bp);
    rb1 = *(const float4*)(Bp + (size_t)8 * N);

    float c[4][4][4];
#pragma unroll
    for (int i = 0; i < 4; i++)
#pragma unroll
        for (int j = 0; j < 4; j++)
#pragma unroll
            for (int q = 0; q < 4; q++) c[i][j][q] = 0.f;

#define STS_STAGE(s)                                                          \
    do {                                                                      \
        As[s][akb + 0][am] = ftf(ra0.x);                                      \
        As[s][akb + 1][am] = ftf(ra0.y);                                      \
        As[s][akb + 2][am] = ftf(ra0.z);                                      \
        As[s][akb + 3][am] = ftf(ra0.w);                                      \
        As[s][akb + 4][am] = ftf(ra1.x);                                      \
        As[s][akb + 5][am] = ftf(ra1.y);                                      \
        As[s][akb + 6][am] = ftf(ra1.z);                                      \
        As[s][akb + 7][am] = ftf(ra1.w);                                      \
        float4 cb0 = make_float4(ftf(rb0.x), ftf(rb0.y), ftf(rb0.z), ftf(rb0.w)); \
        float4 cb1 = make_float4(ftf(rb1.x), ftf(rb1.y), ftf(rb1.z), ftf(rb1.w)); \
        *(float4*)&Bs[s][bkb][bc4]     = cb0;                                 \
        *(float4*)&Bs[s][bkb + 8][bc4] = cb1;                                 \
    } while (0)

    STS_STAGE(0);
    __syncthreads();

    int st = 0;
    for (int k0 = 0; k0 < K; k0 += 16) {
        const int kn = k0 + 16;
        const bool more = kn < K;
        if (more) {
            ra0 = *(const float4*)(Ap + kn);
            ra1 = *(const float4*)(Ap + kn + 4);
            rb0 = *(const float4*)(Bp + (size_t)kn * N);
            rb1 = *(const float4*)(Bp + (size_t)(kn + 8) * N);
        }
#pragma unroll
        for (int kk = 0; kk < 16; kk += 8) {
            uint32_t af[4][4], bf[4][2];
#pragma unroll
            for (int mi = 0; mi < 4; mi++) {
                int m0 = wr * 64 + mi * 16 + tg;
                af[mi][0] = __float_as_uint(As[st][kk + tq][m0]);
                af[mi][1] = __float_as_uint(As[st][kk + tq][m0 + 8]);
                af[mi][2] = __float_as_uint(As[st][kk + tq + 4][m0]);
                af[mi][3] = __float_as_uint(As[st][kk + tq + 4][m0 + 8]);
            }
#pragma unroll
            for (int ni = 0; ni < 4; ni++) {
                int n0 = wc * 32 + ni * 8 + tg;
                bf[ni][0] = __float_as_uint(Bs[st][kk + tq][n0]);
                bf[ni][1] = __float_as_uint(Bs[st][kk + tq + 4][n0]);
            }
#pragma unroll
            for (int mi = 0; mi < 4; mi++)
#pragma unroll
                for (int ni = 0; ni < 4; ni++)
                    mma_tf32(c[mi][ni], af[mi], bf[ni]);
        }
        if (more) {
            STS_STAGE(st ^ 1);
            __syncthreads();
            st ^= 1;
        }
    }
#undef STS_STAGE

    // epilogue
#pragma unroll
    for (int mi = 0; mi < 4; mi++) {
        int r0 = blockIdx.y * 128 + wr * 64 + mi * 16 + tg;
        int r1 = r0 + 8;
#pragma unroll
        for (int ni = 0; ni < 4; ni++) {
            int cc = blockIdx.x * 128 + wc * 32 + ni * 8 + tq * 2;
            float v00 = c[mi][ni][0], v01 = c[mi][ni][1];
            float v10 = c[mi][ni][2], v11 = c[mi][ni][3];
            if (bias) {
                float b0v = bias[cc], b1v = bias[cc + 1];
                v00 += b0v; v01 += b1v; v10 += b0v; v11 += b1v;
            }
            if (EPI == 1) {
                v00 = fmaxf(v00, 0.f); v01 = fmaxf(v01, 0.f);
                v10 = fmaxf(v10, 0.f); v11 = fmaxf(v11, 0.f);
            }
            if (EPI == 2) {
                float2 e0 = *(const float2*)&res[(size_t)r0 * N + cc];
                float2 e1 = *(const float2*)&res[(size_t)r1 * N + cc];
                v00 += e0.x; v01 += e0.y; v10 += e1.x; v11 += e1.y;
            }
            if (EPI == 3) {
                int gs0 = z * M + r0, gs1 = z * M + r1;
                int i0 = sidx[gs0], i1 = sidx[gs1];
                if (i0 >= 0) {
                    float g = sgate[gs0];
                    atomicAdd(&scat[(size_t)i0 * N + cc],     g * v00);
                    atomicAdd(&scat[(size_t)i0 * N + cc + 1], g * v01);
                }
                if (i1 >= 0) {
                    float g = sgate[gs1];
                    atomicAdd(&scat[(size_t)i1 * N + cc],     g * v10);
                    atomicAdd(&scat[(size_t)i1 * N + cc + 1], g * v11);
                }
            } else {
                *(float2*)&Cout[(size_t)r0 * N + cc] = make_float2(v00, v01);
                *(float2*)&Cout[(size_t)r1 * N + cc] = make_float2(v10, v11);
            }
        }
    }
}

// ---------------- attention (flash-style, 1 warp per query row, float4 LDS) ----------------
__global__ __launch_bounds__(256, 1) void attn_kernel(const float* __restrict__ qkv,
                                                      float* __restrict__ aout) {
    __shared__ float Ks[64][68];
    __shared__ float Vs[64][68];
    int bh = blockIdx.y;
    int b = bh >> 4, h = bh & 15;
    int warp = threadIdx.x >> 5, lane = threadIdx.x & 31;
    int t = blockIdx.x * 8 + warp;

    const float* qp = qkv + ((size_t)(b * TSEQ + t)) * 3072 + h * 64;
    float4 q4[16];
#pragma unroll
    for (int d4 = 0; d4 < 16; d4++) q4[d4] = *(const float4*)(qp + d4 * 4);

    float m = -1e30f, l = 0.f;
    float4 acc4[16];
#pragma unroll
    for (int d4 = 0; d4 < 16; d4++) acc4[d4] = make_float4(0.f, 0.f, 0.f, 0.f);

    const float* kbase = qkv + (size_t)b * TSEQ * 3072 + 1024 + h * 64;
    const float* vbase = kbase + 1024;

    for (int s0 = 0; s0 < TSEQ; s0 += 64) {
        __syncthreads();
        for (int i = threadIdx.x; i < 64 * 16; i += 256) {
            int j = i >> 4, dv = (i & 15) << 2;
            float4 kv = *(const float4*)(kbase + (size_t)(s0 + j) * 3072 + dv);
            float4 vv = *(const float4*)(vbase + (size_t)(s0 + j) * 3072 + dv);
            *(float4*)&Ks[j][dv] = kv;
            *(float4*)&Vs[j][dv] = vv;
        }
        __syncthreads();
#pragma unroll
        for (int jj = 0; jj < 2; jj++) {
            int j = lane + (jj << 5);
            float sc = 0.f;
#pragma unroll
            for (int d4 = 0; d4 < 16; d4++) {
                float4 kf = *(const float4*)&Ks[j][d4 * 4];
                sc = fmaf(q4[d4].x, kf.x, sc);
                sc = fmaf(q4[d4].y, kf.y, sc);
                sc = fmaf(q4[d4].z, kf.z, sc);
                sc = fmaf(q4[d4].w, kf.w, sc);
            }
            sc *= 0.125f;
            if (sc > m) {
                float r = __expf(m - sc);
                l = l * r + 1.f;
#pragma unroll
                for (int d4 = 0; d4 < 16; d4++) {
                    float4 vf = *(const float4*)&Vs[j][d4 * 4];
                    acc4[d4].x = acc4[d4].x * r + vf.x;
                    acc4[d4].y = acc4[d4].y * r + vf.y;
                    acc4[d4].z = acc4[d4].z * r + vf.z;
                    acc4[d4].w = acc4[d4].w * r + vf.w;
                }
                m = sc;
            } else {
                float pp = __expf(sc - m);
                l += pp;
#pragma unroll
                for (int d4 = 0; d4 < 16; d4++) {
                    float4 vf = *(const float4*)&Vs[j][d4 * 4];
                    acc4[d4].x = fmaf(pp, vf.x, acc4[d4].x);
                    acc4[d4].y = fmaf(pp, vf.y, acc4[d4].y);
                    acc4[d4].z = fmaf(pp, vf.z, acc4[d4].z);
                    acc4[d4].w = fmaf(pp, vf.w, acc4[d4].w);
                }
            }
        }
    }
    // merge per-lane partial softmaxes
    float M = m;
    for (int o = 16; o; o >>= 1) M = fmaxf(M, __shfl_xor_sync(~0u, M, o));
    float f = __expf(m - M);
    float lf = l * f;
    for (int o = 16; o; o >>= 1) lf += __shfl_xor_sync(~0u, lf, o);
    float invL = 1.f / lf;

    // write through the reference's transpose/reshape permutation
    float* ab = aout + (size_t)b * TSEQ * CDIM;
    int fbase = h * 131072 + t * 64;
    const float* accs = (const float*)acc4;
#pragma unroll
    for (int d = 0; d < 64; d++) {
        float vs = accs[d] * f;
        for (int o = 16; o; o >>= 1) vs += __shfl_xor_sync(~0u, vs, o);
        if (lane == (d & 31)) {
            int fi = fbase + d;
            ab[(size_t)(fi & 2047) * CDIM + (fi >> 11)] = vs * invL;
        }
    }
}

// ---------------- routing GEMV (warp per token) ----------------
__global__ __launch_bounds__(256) void route_kernel(const float* __restrict__ wr,
                                                    const float* __restrict__ br,
                                                    const float* __restrict__ wn,
                                                    const float* __restrict__ bn) {
    int warp = threadIdx.x >> 5, lane = threadIdx.x & 31;
    int n = blockIdx.x * 8 + warp;
    const float* hp = g_h2 + (size_t)n * CDIM;
    float pr[8], pn[8];
#pragma unroll
    for (int e = 0; e < 8; e++) { pr[e] = 0.f; pn[e] = 0.f; }
    for (int c = lane; c < CDIM; c += 32) {
        float hv = hp[c];
#pragma unroll
        for (int e = 0; e < 8; e++) {
            pr[e] += hv * wr[c * 8 + e];
            pn[e] += hv * wn[c * 8 + e];
        }
    }
#pragma unroll
    for (int e = 0; e < 8; e++) {
        for (int o = 16; o; o >>= 1) {
            pr[e] += __shfl_xor_sync(~0u, pr[e], o);
            pn[e] += __shfl_xor_sync(~0u, pn[e], o);
        }
    }
    if (lane == 0) {
#pragma unroll
        for (int e = 0; e < 8; e++) {
            g_logits[n * 8 + e]  = pr[e] + br[e];
            g_nlogits[n * 8 + e] = pn[e] + bn[e];
        }
    }
}

// ---------------- per-token routing epilogue + entropy ----------------
__global__ __launch_bounds__(256) void route_post_kernel(const float* __restrict__ noise) {
    __shared__ float red[8];
    int n = blockIdx.x * blockDim.x + threadIdx.x;
    float noisy[8];
    float mx = -1e30f;
#pragma unroll
    for (int e = 0; e < 8; e++) {
        float nl = g_nlogits[n * 8 + e];
        float sp = log1pf(expf(-fabsf(nl))) + fmaxf(nl, 0.f);   // softplus
        float v = g_logits[n * 8 + e] + noise[n * 8 + e] * sp;
        noisy[e] = v;
        mx = fmaxf(mx, v);
    }
    float s = 0.f, p[8];
#pragma unroll
    for (int e = 0; e < 8; e++) { p[e] = expf(noisy[e] - mx); s += p[e]; }
    float inv = 1.f / s, ent = 0.f;
#pragma unroll
    for (int e = 0; e < 8; e++) { float pe = p[e] * inv; ent -= pe * logf(pe + 1e-8f); }

    int i0 = 0;
#pragma unroll
    for (int e = 1; e < 8; e++) if (noisy[e] > noisy[i0]) i0 = e;
    int i1 = (i0 == 0) ? 1 : 0;
#pragma unroll
    for (int e = 0; e < 8; e++) if (e != i0 && noisy[e] > noisy[i1]) i1 = e;
    float dgl = expf(noisy[i1] - noisy[i0]);
    float g0 = 1.f / (1.f + dgl);
    float g1 = dgl * g0;
    g_sel[n] = i0 | (i1 << 8);
    g_gate[2 * n] = g0;
    g_gate[2 * n + 1] = g1;

    // entropy block reduce -> atomic
    float es = ent;
    for (int o = 16; o; o >>= 1) es += __shfl_xor_sync(~0u, es, o);
    int lane = threadIdx.x & 31, wid = threadIdx.x >> 5;
    if (lane == 0) red[wid] = es;
    __syncthreads();
    if (threadIdx.x < 8) {
        float t = red[threadIdx.x];
        for (int o = 4; o; o >>= 1) t += __shfl_xor_sync(0xffu, t, o);
        if (threadIdx.x == 0) atomicAdd(&g_ent, t);
    }
}

// ---------------- ordered capacity assignment (1 warp, ballot scan) ----------------
__global__ void assign_kernel() {
    int lane = threadIdx.x;
    int cnt[8];
#pragma unroll
    for (int e = 0; e < 8; e++) cnt[e] = 0;
    unsigned lt = (1u << lane) - 1u;
    for (int n0 = 0; n0 < NTOK; n0 += 32) {
        int n = n0 + lane;
        int sel = g_sel[n];
        int e0 = sel & 255, e1 = (sel >> 8) & 255;
        float g0 = g_gate[2 * n], g1 = g_gate[2 * n + 1];
#pragma unroll
        for (int e = 0; e < 8; e++) {
            bool mt = (e0 == e) || (e1 == e);
            unsigned mask = __ballot_sync(~0u, mt);
            if (mt) {
                int r = cnt[e] + __popc(mask & lt);
                if (r < CAP) {
                    g_slot_idx[e * CAP + r]  = n;
                    g_slot_gate[e * CAP + r] = (e0 == e) ? g0 : g1;
                }
            }
            cnt[e] += __popc(mask);
        }
    }
#pragma unroll
    for (int e = 0; e < 8; e++) {
        for (int r = cnt[e] + lane; r < CAP; r += 32) {
            g_slot_idx[e * CAP + r]  = -1;
            g_slot_gate[e * CAP + r] = 0.f;
        }
    }
}

// ---------------- gather tokens into expert buffers ----------------
__global__ __launch_bounds__(256) void gather_kernel() {
    int s = blockIdx.x;
    int idx = g_slot_idx[s];
    float4* dst = (float4*)(g_xe + (size_t)s * CDIM);
    int t = threadIdx.x;
    if (idx >= 0) {
        const float4* src = (const float4*)(g_h2 + (size_t)idx * CDIM);
        dst[t] = src[t];
    } else {
        dst[t] = make_float4(0.f, 0.f, 0.f, 0.f);
    }
}

// ---------------- final: out = x2 + updates ; tail = entropy/N ----------------
__global__ void final_kernel(float* __restrict__ out, int out_size) {
    int i = blockIdx.x * blockDim.x + threadIdx.x;
    if (i < NTOK * CDIM) out[i] = g_x2[i] + g_upd[i];
    else if (i < out_size) out[i] = g_ent * (1.f / NTOK);
}

// ---------------- host launcher ----------------
static float* symf(const void* s) { void* p = nullptr; cudaGetSymbolAddress(&p, s); return (float*)p; }
static int*   symi(const void* s) { void* p = nullptr; cudaGetSymbolAddress(&p, s); return (int*)p; }

extern "C" void kernel_launch(void* const* d_in, const int* in_sizes, int n_in,
                              void* d_out, int out_size) {
    const float* x       = (const float*)d_in[0];
    const float* noise   = (const float*)d_in[1];
    const float* gamma1  = (const float*)d_in[2];
    const float* beta1   = (const float*)d_in[3];
    const float* gamma2  = (const float*)d_in[4];
    const float* beta2   = (const float*)d_in[5];
    const float* w_qkv   = (const float*)d_in[6];
    const float* w_out   = (const float*)d_in[7];
    const float* w_route = (const float*)d_in[8];
    const float* b_route = (const float*)d_in[9];
    const float* w_noise = (const float*)d_in[10];
    const float* b_noise = (const float*)d_in[11];
    const float* w1      = (const float*)d_in[12];
    const float* b1      = (const float*)d_in[13];
    const float* w2      = (const float*)d_in[14];
    const float* b2      = (const float*)d_in[15];
    float* out = (float*)d_out;

    float* p_h1   = symf(g_h1);
    float* p_qkv  = symf(g_qkv);
    float* p_attn = symf(g_attn);
    float* p_x2   = symf(g_x2);
    float* p_h2   = symf(g_h2);
    float* p_xe   = symf(g_xe);
    float* p_hid  = symf(g_hid);
    float* p_upd  = symf(g_upd);
    int*   p_sidx = symi(g_slot_idx);
    float* p_sg   = symf(g_slot_gate);

    // 0) zero updates + entropy
    zero_kernel<<<NTOK * CDIM / 4 / 256, 256>>>();
    // 1) ln1
    ln_kernel<<<NTOK, 256>>>(x, gamma1, beta1, p_h1);
    // 2) qkv = h1 @ w_qkv  [4096 x 3072 x 1024]
    tgemm_kernel<0><<<dim3(3072 / 128, 4096 / 128, 1), 256>>>(
        p_h1, w_qkv, p_qkv, 4096, 3072, 1024,
        nullptr, nullptr, nullptr, nullptr, nullptr, 0, 0, 0, 0);
    // 3) attention -> permuted activation
    attn_kernel<<<dim3(TSEQ / 8, BSZ * NHEADS), 256>>>(p_qkv, p_attn);
    // 4) x2 = x + attn @ w_out  [4096 x 1024 x 1024]
    tgemm_kernel<2><<<dim3(1024 / 128, 4096 / 128, 1), 256>>>(
        p_attn, w_out, p_x2, 4096, 1024, 1024,
        nullptr, x, nullptr, nullptr, nullptr, 0, 0, 0, 0);
    // 5) ln2
    ln_kernel<<<NTOK, 256>>>(p_x2, gamma2, beta2, p_h2);
    // 6) routing GEMV
    route_kernel<<<NTOK / 8, 256>>>(w_route, b_route, w_noise, b_noise);
    // 7) routing epilogue (noisy top-2, gates, entropy)
    route_post_kernel<<<NTOK / 256, 256>>>(noise);
    // 8) ordered capacity assignment
    assign_kernel<<<1, 32>>>();
    // 9) gather expert inputs
    gather_kernel<<<NEXP * CAP, 256>>>();
    // 10) hid = relu(xe @ w1 + b1)  per expert [1024 x 4096 x 1024]
    tgemm_kernel<1><<<dim3(4096 / 128, 1024 / 128, NEXP), 256>>>(
        p_xe, w1, p_hid, 1024, 4096, 1024,
        b1, nullptr, nullptr, nullptr, nullptr,
        (size_t)CAP * CDIM, (size_t)CDIM * DFF, (size_t)CAP * DFF, DFF);
    // 11) yo = hid @ w2 + b2, gated atomic scatter into updates [1024 x 1024 x 4096]
    tgemm_kernel<3><<<dim3(1024 / 128, 1024 / 128, NEXP), 256>>>(
        p_hid, w2, nullptr, 1024, 1024, 4096,
        b2, nullptr, p_sidx, p_sg, p_upd,
        (size_t)CAP * DFF, (size_t)DFF * CDIM, 0, CDIM);
    // 12) final add + entropy tail
    final_kernel<<<(out_size + 255) / 256, 256>>>(out, out_size);
}

// round 4
// speedup vs baseline: 3.3569x; 2.3770x over previous
#include <cuda_runtime.h>
#include <math.h>
#include <stdint.h>

// Problem constants
#define NTOK 4096          // B*T = 2*2048
#define CDIM 1024          // n_embed
#define NEXP 8
#define DFF  4096
#define CAP  1024          // NTOK*2/8
#define NHEADS 16
#define HD   64
#define TSEQ 2048
#define BSZ  2

// ---------------- scratch (device globals; no allocations) ----------------
__device__ float g_h1   [NTOK * CDIM];
__device__ float g_qkv  [NTOK * 3 * CDIM];
__device__ float g_attn [NTOK * CDIM];     // permuted pre-projection activation
__device__ float g_x2   [NTOK * CDIM];     // x + attn_proj
__device__ float g_h2   [NTOK * CDIM];     // ln2(x2)
__device__ float g_logits [NTOK * NEXP];
__device__ float g_nlogits[NTOK * NEXP];
__device__ int   g_sel  [NTOK];            // e0 | (e1<<8)
__device__ float g_gate [NTOK * 2];
__device__ int   g_slot_idx [NEXP * CAP];
__device__ float g_slot_gate[NEXP * CAP];
__device__ float g_xe  [NEXP * CAP * CDIM];
__device__ float g_hid [(size_t)NEXP * CAP * DFF];
__device__ float g_upd [NTOK * CDIM];
__device__ float g_ent;

// ---------------- helpers ----------------
__device__ __forceinline__ float ftf(float x) {
    float r;
    asm("cvt.rna.tf32.f32 %0, %1;" : "=f"(r) : "f"(x));
    return r;
}

__device__ __forceinline__ void mma_tf32(float c[4], const uint32_t a[4], const uint32_t b[2]) {
    asm volatile(
        "mma.sync.aligned.m16n8k8.row.col.f32.tf32.tf32.f32 "
        "{%0,%1,%2,%3},{%4,%5,%6,%7},{%8,%9},{%0,%1,%2,%3};"
        : "+f"(c[0]), "+f"(c[1]), "+f"(c[2]), "+f"(c[3])
        : "r"(a[0]), "r"(a[1]), "r"(a[2]), "r"(a[3]), "r"(b[0]), "r"(b[1]));
}

// ---------------- zero scratch ----------------
__global__ void zero_kernel() {
    size_t i = (size_t)blockIdx.x * blockDim.x + threadIdx.x;
    ((float4*)g_upd)[i] = make_float4(0.f, 0.f, 0.f, 0.f);
    if (i == 0) g_ent = 0.f;
}

// ---------------- layernorm (1 block per row, 256 threads) ----------------
__global__ __launch_bounds__(256) void ln_kernel(const float* __restrict__ x,
                                                 const float* __restrict__ gam,
                                                 const float* __restrict__ bet,
                                                 float* __restrict__ out) {
    __shared__ float red[8];
    __shared__ float s_mu, s_rs;
    int row = blockIdx.x, tid = threadIdx.x;
    const float* xr = x + (size_t)row * CDIM;
    float v[4];
    float s = 0.f;
#pragma unroll
    for (int i = 0; i < 4; i++) { v[i] = xr[tid + i * 256]; s += v[i]; }
    for (int o = 16; o; o >>= 1) s += __shfl_xor_sync(~0u, s, o);
    if ((tid & 31) == 0) red[tid >> 5] = s;
    __syncthreads();
    if (tid < 8) {
        float t = red[tid];
        for (int o = 4; o; o >>= 1) t += __shfl_xor_sync(0xffu, t, o);
        if (tid == 0) s_mu = t * (1.f / CDIM);
    }
    __syncthreads();
    float mu = s_mu;
    float s2 = 0.f;
#pragma unroll
    for (int i = 0; i < 4; i++) { float d = v[i] - mu; s2 += d * d; }
    for (int o = 16; o; o >>= 1) s2 += __shfl_xor_sync(~0u, s2, o);
    if ((tid & 31) == 0) red[tid >> 5] = s2;
    __syncthreads();
    if (tid < 8) {
        float t = red[tid];
        for (int o = 4; o; o >>= 1) t += __shfl_xor_sync(0xffu, t, o);
        if (tid == 0) s_rs = rsqrtf(t * (1.f / CDIM) + 1e-5f);
    }
    __syncthreads();
    float rs = s_rs;
    float* orow = out + (size_t)row * CDIM;
#pragma unroll
    for (int i = 0; i < 4; i++) {
        int c = tid + i * 256;
        orow[c] = (v[i] - mu) * rs * gam[c] + bet[c];
    }
}

// ---------------- tf32 tensor-core GEMM 128x128x16, double-buffered ----------------
// EPI: 0 = store (+bias), 1 = store relu(+bias), 2 = store + residual,
//      3 = gated atomic scatter into scat[] using slot tables (bias added first)
template <int EPI>
__global__ __launch_bounds__(256) void tgemm_kernel(
    const float* __restrict__ A, const float* __restrict__ B, float* __restrict__ Cout,
    int M, int N, int K,
    const float* __restrict__ bias, const float* __restrict__ res,
    const int* __restrict__ sidx, const float* __restrict__ sgate,
    float* __restrict__ scat,
    size_t sA, size_t sB, size_t sC, int sBias)
{
    __shared__ float As[2][16][132];   // [k][m], padded
    __shared__ float Bs[2][16][132];   // [k][n], padded

    const int z = blockIdx.z;
    A += (size_t)z * sA;
    B += (size_t)z * sB;
    if (Cout) Cout += (size_t)z * sC;
    if (bias) bias += (size_t)z * sBias;

    const int tid  = threadIdx.x;
    const int lane = tid & 31, wid = tid >> 5;
    const int wr = wid >> 2, wc = wid & 3;      // warp tile: 64(M) x 32(N)
    const int tg = lane >> 2, tq = lane & 3;

    const int am  = tid & 127;
    const int akb = (tid >> 7) << 3;
    const float* Ap = A + (size_t)(blockIdx.y * 128 + am) * K + akb;
    const int bkb = tid >> 5;
    const int bc4 = (tid & 31) << 2;
    const float* Bp = B + (size_t)bkb * N + blockIdx.x * 128 + bc4;

    float4 ra0, ra1, rb0, rb1;
    ra0 = *(const float4*)(Ap);
    ra1 = *(const float4*)(Ap + 4);
    rb0 = *(const float4*)(Bp);
    rb1 = *(const float4*)(Bp + (size_t)8 * N);

    float c[4][4][4];
#pragma unroll
    for (int i = 0; i < 4; i++)
#pragma unroll
        for (int j = 0; j < 4; j++)
#pragma unroll
            for (int q = 0; q < 4; q++) c[i][j][q] = 0.f;

#define STS_STAGE(s)                                                          \
    do {                                                                      \
        As[s][akb + 0][am] = ftf(ra0.x);                                      \
        As[s][akb + 1][am] = ftf(ra0.y);                                      \
        As[s][akb + 2][am] = ftf(ra0.z);                                      \
        As[s][akb + 3][am] = ftf(ra0.w);                                      \
        As[s][akb + 4][am] = ftf(ra1.x);                                      \
        As[s][akb + 5][am] = ftf(ra1.y);                                      \
        As[s][akb + 6][am] = ftf(ra1.z);                                      \
        As[s][akb + 7][am] = ftf(ra1.w);                                      \
        float4 cb0 = make_float4(ftf(rb0.x), ftf(rb0.y), ftf(rb0.z), ftf(rb0.w)); \
        float4 cb1 = make_float4(ftf(rb1.x), ftf(rb1.y), ftf(rb1.z), ftf(rb1.w)); \
        *(float4*)&Bs[s][bkb][bc4]     = cb0;                                 \
        *(float4*)&Bs[s][bkb + 8][bc4] = cb1;                                 \
    } while (0)

    STS_STAGE(0);
    __syncthreads();

    int st = 0;
    for (int k0 = 0; k0 < K; k0 += 16) {
        const int kn = k0 + 16;
        const bool more = kn < K;
        if (more) {
            ra0 = *(const float4*)(Ap + kn);
            ra1 = *(const float4*)(Ap + kn + 4);
            rb0 = *(const float4*)(Bp + (size_t)kn * N);
            rb1 = *(const float4*)(Bp + (size_t)(kn + 8) * N);
        }
#pragma unroll
        for (int kk = 0; kk < 16; kk += 8) {
            uint32_t af[4][4], bf[4][2];
#pragma unroll
            for (int mi = 0; mi < 4; mi++) {
                int m0 = wr * 64 + mi * 16 + tg;
                af[mi][0] = __float_as_uint(As[st][kk + tq][m0]);
                af[mi][1] = __float_as_uint(As[st][kk + tq][m0 + 8]);
                af[mi][2] = __float_as_uint(As[st][kk + tq + 4][m0]);
                af[mi][3] = __float_as_uint(As[st][kk + tq + 4][m0 + 8]);
            }
#pragma unroll
            for (int ni = 0; ni < 4; ni++) {
                int n0 = wc * 32 + ni * 8 + tg;
                bf[ni][0] = __float_as_uint(Bs[st][kk + tq][n0]);
                bf[ni][1] = __float_as_uint(Bs[st][kk + tq + 4][n0]);
            }
#pragma unroll
            for (int mi = 0; mi < 4; mi++)
#pragma unroll
                for (int ni = 0; ni < 4; ni++)
                    mma_tf32(c[mi][ni], af[mi], bf[ni]);
        }
        if (more) {
            STS_STAGE(st ^ 1);
            __syncthreads();
            st ^= 1;
        }
    }
#undef STS_STAGE

    // epilogue
#pragma unroll
    for (int mi = 0; mi < 4; mi++) {
        int r0 = blockIdx.y * 128 + wr * 64 + mi * 16 + tg;
        int r1 = r0 + 8;
#pragma unroll
        for (int ni = 0; ni < 4; ni++) {
            int cc = blockIdx.x * 128 + wc * 32 + ni * 8 + tq * 2;
            float v00 = c[mi][ni][0], v01 = c[mi][ni][1];
            float v10 = c[mi][ni][2], v11 = c[mi][ni][3];
            if (bias) {
                float b0v = bias[cc], b1v = bias[cc + 1];
                v00 += b0v; v01 += b1v; v10 += b0v; v11 += b1v;
            }
            if (EPI == 1) {
                v00 = fmaxf(v00, 0.f); v01 = fmaxf(v01, 0.f);
                v10 = fmaxf(v10, 0.f); v11 = fmaxf(v11, 0.f);
            }
            if (EPI == 2) {
                float2 e0 = *(const float2*)&res[(size_t)r0 * N + cc];
                float2 e1 = *(const float2*)&res[(size_t)r1 * N + cc];
                v00 += e0.x; v01 += e0.y; v10 += e1.x; v11 += e1.y;
            }
            if (EPI == 3) {
                int gs0 = z * M + r0, gs1 = z * M + r1;
                int i0 = sidx[gs0], i1 = sidx[gs1];
                if (i0 >= 0) {
                    float g = sgate[gs0];
                    atomicAdd(&scat[(size_t)i0 * N + cc],     g * v00);
                    atomicAdd(&scat[(size_t)i0 * N + cc + 1], g * v01);
                }
                if (i1 >= 0) {
                    float g = sgate[gs1];
                    atomicAdd(&scat[(size_t)i1 * N + cc],     g * v10);
                    atomicAdd(&scat[(size_t)i1 * N + cc + 1], g * v11);
                }
            } else {
                *(float2*)&Cout[(size_t)r0 * N + cc] = make_float2(v00, v01);
                *(float2*)&Cout[(size_t)r1 * N + cc] = make_float2(v10, v11);
            }
        }
    }
}

// ---------------- tensor-core flash attention ----------------
// Block: 128 queries x one (b,h). 8 warps, each 16 query rows x full 64 head dim.
// K/V staged in smem (stride 72 -> conflict-free for both access patterns).
__global__ __launch_bounds__(256) void attn_tc_kernel(const float* __restrict__ qkv,
                                                      float* __restrict__ aout) {
    __shared__ float Ks[64][72];
    __shared__ float Vs[64][72];
    const int bh = blockIdx.y;
    const int b = bh >> 4, h = bh & 15;
    const int tid = threadIdx.x, lane = tid & 31, w = tid >> 5;
    const int tg = lane >> 2, tq = lane & 3;
    const int q0 = blockIdx.x * 128 + w * 16;

    const float* qbase = qkv + (size_t)b * TSEQ * 3072 + h * 64;

    // Q a-fragments, scale folded in, tf32-converted, register-resident
    uint32_t qa[8][4];
    {
        const float* qr0 = qbase + (size_t)(q0 + tg) * 3072;
        const float* qr1 = qbase + (size_t)(q0 + tg + 8) * 3072;
#pragma unroll
        for (int kk = 0; kk < 8; kk++) {
            qa[kk][0] = __float_as_uint(ftf(qr0[kk * 8 + tq]     * 0.125f));
            qa[kk][1] = __float_as_uint(ftf(qr1[kk * 8 + tq]     * 0.125f));
            qa[kk][2] = __float_as_uint(ftf(qr0[kk * 8 + tq + 4] * 0.125f));
            qa[kk][3] = __float_as_uint(ftf(qr1[kk * 8 + tq + 4] * 0.125f));
        }
    }

    float oacc[8][4];
#pragma unroll
    for (int dt = 0; dt < 8; dt++)
#pragma unroll
        for (int i = 0; i < 4; i++) oacc[dt][i] = 0.f;
    float m0 = -1e30f, m1 = -1e30f, l0 = 0.f, l1 = 0.f;

    const float* kbase = qbase + 1024;
    const float* vbase = qbase + 2048;
    const int slo = (tg << 2) + (tq >> 1);
    const int shi = slo + 2;

    for (int s0 = 0; s0 < TSEQ; s0 += 64) {
        __syncthreads();
        for (int i = tid; i < 64 * 16; i += 256) {
            int j = i >> 4, dv = (i & 15) << 2;
            float4 kv = *(const float4*)(kbase + (size_t)(s0 + j) * 3072 + dv);
            float4 vv = *(const float4*)(vbase + (size_t)(s0 + j) * 3072 + dv);
            Ks[j][dv] = ftf(kv.x); Ks[j][dv + 1] = ftf(kv.y);
            Ks[j][dv + 2] = ftf(kv.z); Ks[j][dv + 3] = ftf(kv.w);
            Vs[j][dv] = ftf(vv.x); Vs[j][dv + 1] = ftf(vv.y);
            Vs[j][dv + 2] = ftf(vv.z); Vs[j][dv + 3] = ftf(vv.w);
        }
        __syncthreads();

        // S = Q * K^T  (per warp: 16 x 64)
        float s[8][4];
#pragma unroll
        for (int nt = 0; nt < 8; nt++) {
            s[nt][0] = s[nt][1] = s[nt][2] = s[nt][3] = 0.f;
#pragma unroll
            for (int kk = 0; kk < 8; kk++) {
                uint32_t bb[2] = {
                    __float_as_uint(Ks[nt * 8 + tg][kk * 8 + tq]),
                    __float_as_uint(Ks[nt * 8 + tg][kk * 8 + tq + 4])};
                mma_tf32(s[nt], qa[kk], bb);
            }
        }

        // online softmax (rows tg / tg+8, spread over lanes slo group)
        float rm0 = -1e30f, rm1 = -1e30f;
#pragma unroll
        for (int nt = 0; nt < 8; nt++) {
            rm0 = fmaxf(rm0, fmaxf(s[nt][0], s[nt][1]));
            rm1 = fmaxf(rm1, fmaxf(s[nt][2], s[nt][3]));
        }
        rm0 = fmaxf(rm0, __shfl_xor_sync(~0u, rm0, 1));
        rm0 = fmaxf(rm0, __shfl_xor_sync(~0u, rm0, 2));
        rm1 = fmaxf(rm1, __shfl_xor_sync(~0u, rm1, 1));
        rm1 = fmaxf(rm1, __shfl_xor_sync(~0u, rm1, 2));
        float mn0 = fmaxf(m0, rm0), mn1 = fmaxf(m1, rm1);
        float sc0 = __expf(m0 - mn0), sc1 = __expf(m1 - mn1);
        m0 = mn0; m1 = mn1;
        float rs0 = 0.f, rs1 = 0.f;
#pragma unroll
        for (int nt = 0; nt < 8; nt++) {
            s[nt][0] = __expf(s[nt][0] - mn0);
            s[nt][1] = __expf(s[nt][1] - mn0);
            s[nt][2] = __expf(s[nt][2] - mn1);
            s[nt][3] = __expf(s[nt][3] - mn1);
            rs0 += s[nt][0] + s[nt][1];
            rs1 += s[nt][2] + s[nt][3];
        }
        rs0 += __shfl_xor_sync(~0u, rs0, 1);
        rs0 += __shfl_xor_sync(~0u, rs0, 2);
        rs1 += __shfl_xor_sync(~0u, rs1, 1);
        rs1 += __shfl_xor_sync(~0u, rs1, 2);
        l0 = l0 * sc0 + rs0;
        l1 = l1 * sc1 + rs1;
#pragma unroll
        for (int dt = 0; dt < 8; dt++) {
            oacc[dt][0] *= sc0; oacc[dt][1] *= sc0;
            oacc[dt][2] *= sc1; oacc[dt][3] *= sc1;
        }

        // O += P * V   (P C-frag -> A-frag relayout via shuffles)
#pragma unroll
        for (int kk = 0; kk < 8; kk++) {
            uint32_t pa[4];
            float e, o;
            e = __shfl_sync(~0u, s[kk][0], slo); o = __shfl_sync(~0u, s[kk][1], slo);
            pa[0] = __float_as_uint((tq & 1) ? o : e);
            e = __shfl_sync(~0u, s[kk][2], slo); o = __shfl_sync(~0u, s[kk][3], slo);
            pa[1] = __float_as_uint((tq & 1) ? o : e);
            e = __shfl_sync(~0u, s[kk][0], shi); o = __shfl_sync(~0u, s[kk][1], shi);
            pa[2] = __float_as_uint((tq & 1) ? o : e);
            e = __shfl_sync(~0u, s[kk][2], shi); o = __shfl_sync(~0u, s[kk][3], shi);
            pa[3] = __float_as_uint((tq & 1) ? o : e);
#pragma unroll
            for (int dt = 0; dt < 8; dt++) {
                uint32_t bb[2] = {
                    __float_as_uint(Vs[kk * 8 + tq][dt * 8 + tg]),
                    __float_as_uint(Vs[kk * 8 + tq + 4][dt * 8 + tg])};
                mma_tf32(oacc[dt], pa, bb);
            }
        }
    }

    // finalize + permuted store: out[(t&31)*64+d][h*64 + (t>>5)]
    float inv0 = 1.f / l0, inv1 = 1.f / l1;
    float* ab = aout + (size_t)b * TSEQ * CDIM;
    int t0 = q0 + tg, t1 = t0 + 8;
    int c0 = h * 64 + (t0 >> 5), r0b = (t0 & 31) * 64;
    int c1 = h * 64 + (t1 >> 5), r1b = (t1 & 31) * 64;
#pragma unroll
    for (int dt = 0; dt < 8; dt++) {
        int d = dt * 8 + tq * 2;
        ab[(size_t)(r0b + d) * CDIM + c0]     = oacc[dt][0] * inv0;
        ab[(size_t)(r0b + d + 1) * CDIM + c0] = oacc[dt][1] * inv0;
        ab[(size_t)(r1b + d) * CDIM + c1]     = oacc[dt][2] * inv1;
        ab[(size_t)(r1b + d + 1) * CDIM + c1] = oacc[dt][3] * inv1;
    }
}

// ---------------- routing GEMV (warp per token) ----------------
__global__ __launch_bounds__(256) void route_kernel(const float* __restrict__ wr,
                                                    const float* __restrict__ br,
                                                    const float* __restrict__ wn,
                                                    const float* __restrict__ bn) {
    int warp = threadIdx.x >> 5, lane = threadIdx.x & 31;
    int n = blockIdx.x * 8 + warp;
    const float* hp = g_h2 + (size_t)n * CDIM;
    float pr[8], pn[8];
#pragma unroll
    for (int e = 0; e < 8; e++) { pr[e] = 0.f; pn[e] = 0.f; }
    for (int c = lane; c < CDIM; c += 32) {
        float hv = hp[c];
#pragma unroll
        for (int e = 0; e < 8; e++) {
            pr[e] += hv * wr[c * 8 + e];
            pn[e] += hv * wn[c * 8 + e];
        }
    }
#pragma unroll
    for (int e = 0; e < 8; e++) {
        for (int o = 16; o; o >>= 1) {
            pr[e] += __shfl_xor_sync(~0u, pr[e], o);
            pn[e] += __shfl_xor_sync(~0u, pn[e], o);
        }
    }
    if (lane == 0) {
#pragma unroll
        for (int e = 0; e < 8; e++) {
            g_logits[n * 8 + e]  = pr[e] + br[e];
            g_nlogits[n * 8 + e] = pn[e] + bn[e];
        }
    }
}

// ---------------- per-token routing epilogue + entropy ----------------
__global__ __launch_bounds__(256) void route_post_kernel(const float* __restrict__ noise) {
    __shared__ float red[8];
    int n = blockIdx.x * blockDim.x + threadIdx.x;
    float noisy[8];
    float mx = -1e30f;
#pragma unroll
    for (int e = 0; e < 8; e++) {
        float nl = g_nlogits[n * 8 + e];
        float sp = log1pf(expf(-fabsf(nl))) + fmaxf(nl, 0.f);   // softplus
        float v = g_logits[n * 8 + e] + noise[n * 8 + e] * sp;
        noisy[e] = v;
        mx = fmaxf(mx, v);
    }
    float s = 0.f, p[8];
#pragma unroll
    for (int e = 0; e < 8; e++) { p[e] = expf(noisy[e] - mx); s += p[e]; }
    float inv = 1.f / s, ent = 0.f;
#pragma unroll
    for (int e = 0; e < 8; e++) { float pe = p[e] * inv; ent -= pe * logf(pe + 1e-8f); }

    int i0 = 0;
#pragma unroll
    for (int e = 1; e < 8; e++) if (noisy[e] > noisy[i0]) i0 = e;
    int i1 = (i0 == 0) ? 1 : 0;
#pragma unroll
    for (int e = 0; e < 8; e++) if (e != i0 && noisy[e] > noisy[i1]) i1 = e;
    float dgl = expf(noisy[i1] - noisy[i0]);
    float g0 = 1.f / (1.f + dgl);
    float g1 = dgl * g0;
    g_sel[n] = i0 | (i1 << 8);
    g_gate[2 * n] = g0;
    g_gate[2 * n + 1] = g1;

    float es = ent;
    for (int o = 16; o; o >>= 1) es += __shfl_xor_sync(~0u, es, o);
    int lane = threadIdx.x & 31, wid = threadIdx.x >> 5;
    if (lane == 0) red[wid] = es;
    __syncthreads();
    if (threadIdx.x < 8) {
        float t = red[threadIdx.x];
        for (int o = 4; o; o >>= 1) t += __shfl_xor_sync(0xffu, t, o);
        if (threadIdx.x == 0) atomicAdd(&g_ent, t);
    }
}

// ---------------- ordered capacity assignment (1 warp, ballot scan) ----------------
__global__ void assign_kernel() {
    int lane = threadIdx.x;
    int cnt[8];
#pragma unroll
    for (int e = 0; e < 8; e++) cnt[e] = 0;
    unsigned lt = (1u << lane) - 1u;
    for (int n0 = 0; n0 < NTOK; n0 += 32) {
        int n = n0 + lane;
        int sel = g_sel[n];
        int e0 = sel & 255, e1 = (sel >> 8) & 255;
        float g0 = g_gate[2 * n], g1 = g_gate[2 * n + 1];
#pragma unroll
        for (int e = 0; e < 8; e++) {
            bool mt = (e0 == e) || (e1 == e);
            unsigned mask = __ballot_sync(~0u, mt);
            if (mt) {
                int r = cnt[e] + __popc(mask & lt);
                if (r < CAP) {
                    g_slot_idx[e * CAP + r]  = n;
                    g_slot_gate[e * CAP + r] = (e0 == e) ? g0 : g1;
                }
            }
            cnt[e] += __popc(mask);
        }
    }
#pragma unroll
    for (int e = 0; e < 8; e++) {
        for (int r = cnt[e] + lane; r < CAP; r += 32) {
            g_slot_idx[e * CAP + r]  = -1;
            g_slot_gate[e * CAP + r] = 0.f;
        }
    }
}

// ---------------- gather tokens into expert buffers ----------------
__global__ __launch_bounds__(256) void gather_kernel() {
    int s = blockIdx.x;
    int idx = g_slot_idx[s];
    float4* dst = (float4*)(g_xe + (size_t)s * CDIM);
    int t = threadIdx.x;
    if (idx >= 0) {
        const float4* src = (const float4*)(g_h2 + (size_t)idx * CDIM);
        dst[t] = src[t];
    } else {
        dst[t] = make_float4(0.f, 0.f, 0.f, 0.f);
    }
}

// ---------------- final: out = x2 + updates ; tail = entropy/N ----------------
__global__ void final_kernel(float* __restrict__ out, int out_size) {
    int i = blockIdx.x * blockDim.x + threadIdx.x;
    if (i < NTOK * CDIM) out[i] = g_x2[i] + g_upd[i];
    else if (i < out_size) out[i] = g_ent * (1.f / NTOK);
}

// ---------------- host launcher ----------------
static float* symf(const void* s) { void* p = nullptr; cudaGetSymbolAddress(&p, s); return (float*)p; }
static int*   symi(const void* s) { void* p = nullptr; cudaGetSymbolAddress(&p, s); return (int*)p; }

extern "C" void kernel_launch(void* const* d_in, const int* in_sizes, int n_in,
                              void* d_out, int out_size) {
    const float* x       = (const float*)d_in[0];
    const float* noise   = (const float*)d_in[1];
    const float* gamma1  = (const float*)d_in[2];
    const float* beta1   = (const float*)d_in[3];
    const float* gamma2  = (const float*)d_in[4];
    const float* beta2   = (const float*)d_in[5];
    const float* w_qkv   = (const float*)d_in[6];
    const float* w_out   = (const float*)d_in[7];
    const float* w_route = (const float*)d_in[8];
    const float* b_route = (const float*)d_in[9];
    const float* w_noise = (const float*)d_in[10];
    const float* b_noise = (const float*)d_in[11];
    const float* w1      = (const float*)d_in[12];
    const float* b1      = (const float*)d_in[13];
    const float* w2      = (const float*)d_in[14];
    const float* b2      = (const float*)d_in[15];
    float* out = (float*)d_out;

    float* p_h1   = symf(g_h1);
    float* p_qkv  = symf(g_qkv);
    float* p_attn = symf(g_attn);
    float* p_x2   = symf(g_x2);
    float* p_h2   = symf(g_h2);
    float* p_xe   = symf(g_xe);
    float* p_hid  = symf(g_hid);
    float* p_upd  = symf(g_upd);
    int*   p_sidx = symi(g_slot_idx);
    float* p_sg   = symf(g_slot_gate);

    // 0) zero updates + entropy
    zero_kernel<<<NTOK * CDIM / 4 / 256, 256>>>();
    // 1) ln1
    ln_kernel<<<NTOK, 256>>>(x, gamma1, beta1, p_h1);
    // 2) qkv = h1 @ w_qkv  [4096 x 3072 x 1024]
    tgemm_kernel<0><<<dim3(3072 / 128, 4096 / 128, 1), 256>>>(
        p_h1, w_qkv, p_qkv, 4096, 3072, 1024,
        nullptr, nullptr, nullptr, nullptr, nullptr, 0, 0, 0, 0);
    // 3) tensor-core flash attention -> permuted activation
    attn_tc_kernel<<<dim3(TSEQ / 128, BSZ * NHEADS), 256>>>(p_qkv, p_attn);
    // 4) x2 = x + attn @ w_out  [4096 x 1024 x 1024]
    tgemm_kernel<2><<<dim3(1024 / 128, 4096 / 128, 1), 256>>>(
        p_attn, w_out, p_x2, 4096, 1024, 1024,
        nullptr, x, nullptr, nullptr, nullptr, 0, 0, 0, 0);
    // 5) ln2
    ln_kernel<<<NTOK, 256>>>(p_x2, gamma2, beta2, p_h2);
    // 6) routing GEMV
    route_kernel<<<NTOK / 8, 256>>>(w_route, b_route, w_noise, b_noise);
    // 7) routing epilogue (noisy top-2, gates, entropy)
    route_post_kernel<<<NTOK / 256, 256>>>(noise);
    // 8) ordered capacity assignment
    assign_kernel<<<1, 32>>>();
    // 9) gather expert inputs
    gather_kernel<<<NEXP * CAP, 256>>>();
    // 10) hid = relu(xe @ w1 + b1)  per expert [1024 x 4096 x 1024]
    tgemm_kernel<1><<<dim3(4096 / 128, 1024 / 128, NEXP), 256>>>(
        p_xe, w1, p_hid, 1024, 4096, 1024,
        b1, nullptr, nullptr, nullptr, nullptr,
        (size_t)CAP * CDIM, (size_t)CDIM * DFF, (size_t)CAP * DFF, DFF);
    // 11) yo = hid @ w2 + b2, gated atomic scatter into updates [1024 x 1024 x 4096]
    tgemm_kernel<3><<<dim3(1024 / 128, 1024 / 128, NEXP), 256>>>(
        p_hid, w2, nullptr, 1024, 1024, 4096,
        b2, nullptr, p_sidx, p_sg, p_upd,
        (size_t)CAP * DFF, (size_t)DFF * CDIM, 0, CDIM);
    // 12) final add + entropy tail
    final_kernel<<<(out_size + 255) / 256, 256>>>(out, out_size);
}

// round 6
// speedup vs baseline: 5.4897x; 1.6353x over previous
#include <cuda_runtime.h>
#include <math.h>
#include <stdint.h>

// Problem constants
#define NTOK 4096          // B*T = 2*2048
#define CDIM 1024          // n_embed
#define NEXP 8
#define DFF  4096
#define CAP  1024          // NTOK*2/8
#define NHEADS 16
#define HD   64
#define TSEQ 2048
#define BSZ  2

// GEMM pipeline shared-memory layout (floats):
//   As: 3 stages x 128 rows x 20 (16 k + 4 pad)   = 3*2560
//   Bs: 3 stages x 16 rows x 136 (128 n + 8 pad)  = 3*2176
#define AS_STRIDE 20
#define BS_STRIDE 136
#define AS_STAGE  2560
#define BS_STAGE  2176
#define BS_OFF    7680          // 3 * AS_STAGE
#define SMEM_WORDS (BS_OFF + 3 * BS_STAGE)
#define SMEM_BYTES (SMEM_WORDS * 4)

// ---------------- scratch (device globals; no allocations) ----------------
__device__ float g_h1   [NTOK * CDIM];
__device__ float g_qkv  [NTOK * 3 * CDIM];
__device__ float g_attn [NTOK * CDIM];     // permuted pre-projection activation
__device__ float g_x2   [NTOK * CDIM];     // x + attn_proj
__device__ float g_h2   [NTOK * CDIM];     // ln2(x2)
__device__ float g_logits [NTOK * NEXP];
__device__ float g_nlogits[NTOK * NEXP];
__device__ int   g_sel  [NTOK];            // e0 | (e1<<8)
__device__ float g_gate [NTOK * 2];
__device__ int   g_slot_idx [NEXP * CAP];
__device__ float g_slot_gate[NEXP * CAP];
__device__ float g_zero[CDIM];
__device__ float g_hid [(size_t)NEXP * CAP * DFF];
__device__ float g_upd [NTOK * CDIM];
__device__ float g_ent;

// ---------------- helpers ----------------
__device__ __forceinline__ float ftf(float x) {
    float r;
    asm("cvt.rna.tf32.f32 %0, %1;" : "=f"(r) : "f"(x));
    return r;
}

__device__ __forceinline__ void mma_tf32(float c[4], const uint32_t a[4], const uint32_t b[2]) {
    asm volatile(
        "mma.sync.aligned.m16n8k8.row.col.f32.tf32.tf32.f32 "
        "{%0,%1,%2,%3},{%4,%5,%6,%7},{%8,%9},{%0,%1,%2,%3};"
        : "+f"(c[0]), "+f"(c[1]), "+f"(c[2]), "+f"(c[3])
        : "r"(a[0]), "r"(a[1]), "r"(a[2]), "r"(a[3]), "r"(b[0]), "r"(b[1]));
}

// ---------------- zero scratch ----------------
__global__ void zero_kernel() {
    size_t i = (size_t)blockIdx.x * blockDim.x + threadIdx.x;
    ((float4*)g_upd)[i] = make_float4(0.f, 0.f, 0.f, 0.f);
    if (i < CDIM / 4) ((float4*)g_zero)[i] = make_float4(0.f, 0.f, 0.f, 0.f);
    if (i == 0) g_ent = 0.f;
}

// ---------------- layernorm (1 block per row, 256 threads) ----------------
__global__ __launch_bounds__(256) void ln_kernel(const float* __restrict__ x,
                                                 const float* __restrict__ gam,
                                                 const float* __restrict__ bet,
                                                 float* __restrict__ out) {
    __shared__ float red[8];
    __shared__ float s_mu, s_rs;
    int row = blockIdx.x, tid = threadIdx.x;
    const float* xr = x + (size_t)row * CDIM;
    float v[4];
    float s = 0.f;
#pragma unroll
    for (int i = 0; i < 4; i++) { v[i] = xr[tid + i * 256]; s += v[i]; }
    for (int o = 16; o; o >>= 1) s += __shfl_xor_sync(~0u, s, o);
    if ((tid & 31) == 0) red[tid >> 5] = s;
    __syncthreads();
    if (tid < 8) {
        float t = red[tid];
        for (int o = 4; o; o >>= 1) t += __shfl_xor_sync(0xffu, t, o);
        if (tid == 0) s_mu = t * (1.f / CDIM);
    }
    __syncthreads();
    float mu = s_mu;
    float s2 = 0.f;
#pragma unroll
    for (int i = 0; i < 4; i++) { float d = v[i] - mu; s2 += d * d; }
    for (int o = 16; o; o >>= 1) s2 += __shfl_xor_sync(~0u, s2, o);
    if ((tid & 31) == 0) red[tid >> 5] = s2;
    __syncthreads();
    if (tid < 8) {
        float t = red[tid];
        for (int o = 4; o; o >>= 1) t += __shfl_xor_sync(0xffu, t, o);
        if (tid == 0) s_rs = rsqrtf(t * (1.f / CDIM) + 1e-5f);
    }
    __syncthreads();
    float rs = s_rs;
    float* orow = out + (size_t)row * CDIM;
#pragma unroll
    for (int i = 0; i < 4; i++) {
        int c = tid + i * 256;
        orow[c] = (v[i] - mu) * rs * gam[c] + bet[c];
    }
}

// ---------------- tf32 tensor-core GEMM 128x128x16, 3-stage cp.async ----------------
// EPI: 0 = store (+bias), 1 = store relu(+bias), 2 = store + residual,
//      3 = gated atomic scatter into scat[] using slot tables (bias added first)
// GATHER: A rows indirected through sidx (invalid -> zero row)
template <int EPI, bool GATHER>
__global__ __launch_bounds__(256) void tgemm2_kernel(
    const float* __restrict__ A, const float* __restrict__ B, float* __restrict__ Cout,
    int M, int N, int K,
    const float* __restrict__ bias, const float* __restrict__ res,
    const int* __restrict__ sidx, const float* __restrict__ sgate,
    float* __restrict__ scat, const float* __restrict__ zrow,
    size_t sA, size_t sB, size_t sC, int sBias)
{
    extern __shared__ float dsm[];
    __shared__ const float* arow[128];

    const int z = blockIdx.z;
    if (!GATHER) A += (size_t)z * sA;
    B += (size_t)z * sB;
    if (Cout) Cout += (size_t)z * sC;
    if (bias) bias += (size_t)z * sBias;

    const int tid  = threadIdx.x;
    const int lane = tid & 31, wid = tid >> 5;
    const int wr = wid >> 2, wc = wid & 3;      // warp tile: 64(M) x 32(N)
    const int tg = lane >> 2, tq = lane & 3;

    if (tid < 128) {
        const float* p;
        if (GATHER) {
            int idx = sidx[z * M + blockIdx.y * 128 + tid];
            p = (idx >= 0) ? (A + (size_t)idx * K) : zrow;
        } else {
            p = A + (size_t)(blockIdx.y * 128 + tid) * K;
        }
        arow[tid] = p;
    }
    __syncthreads();

    const uint32_t sbase = (uint32_t)__cvta_generic_to_shared(dsm);
    const float* Bbase = B + blockIdx.x * 128;

#define ISSUE(st, k0)                                                          \
    do {                                                                       \
        _Pragma("unroll")                                                      \
        for (int c2 = 0; c2 < 2; c2++) {                                       \
            int cc_ = tid + c2 * 256;                                          \
            int row_ = cc_ >> 2, kq_ = (cc_ & 3) << 2;                         \
            uint32_t d_ = sbase + (uint32_t)(((st) * AS_STAGE + row_ * AS_STRIDE + kq_) * 4); \
            asm volatile("cp.async.cg.shared.global [%0], [%1], 16;\n"         \
                         :: "r"(d_), "l"(arow[row_] + (k0) + kq_));            \
        }                                                                      \
        _Pragma("unroll")                                                      \
        for (int c2 = 0; c2 < 2; c2++) {                                       \
            int cc_ = tid + c2 * 256;                                          \
            int row_ = cc_ >> 5, col_ = (cc_ & 31) << 2;                       \
            uint32_t d_ = sbase + (uint32_t)((BS_OFF + (st) * BS_STAGE + row_ * BS_STRIDE + col_) * 4); \
            asm volatile("cp.async.cg.shared.global [%0], [%1], 16;\n"         \
                         :: "r"(d_), "l"(Bbase + (size_t)((k0) + row_) * N + col_)); \
        }                                                                      \
    } while (0)

    float c[4][4][4];
#pragma unroll
    for (int i = 0; i < 4; i++)
#pragma unroll
        for (int j = 0; j < 4; j++)
#pragma unroll
            for (int q = 0; q < 4; q++) c[i][j][q] = 0.f;

    const int KT = K >> 4;
    ISSUE(0, 0);
    asm volatile("cp.async.commit_group;\n");
    ISSUE(1, 16);
    asm volatile("cp.async.commit_group;\n");

    for (int it = 0; it < KT; it++) {
        asm volatile("cp.async.wait_group 1;\n");
        __syncthreads();
        if (it + 2 < KT) {
            int stn = (it + 2) % 3;
            ISSUE(stn, (it + 2) * 16);
        }
        asm volatile("cp.async.commit_group;\n");

        const int st = it % 3;
        const float* As = dsm + st * AS_STAGE;
        const float* Bs = dsm + BS_OFF + st * BS_STAGE;
#pragma unroll
        for (int kk = 0; kk < 16; kk += 8) {
            uint32_t af[4][4], bf[4][2];
#pragma unroll
            for (int mi = 0; mi < 4; mi++) {
                int m0 = wr * 64 + mi * 16 + tg;
                af[mi][0] = __float_as_uint(As[m0 * AS_STRIDE + kk + tq]);
                af[mi][1] = __float_as_uint(As[(m0 + 8) * AS_STRIDE + kk + tq]);
                af[mi][2] = __float_as_uint(As[m0 * AS_STRIDE + kk + tq + 4]);
                af[mi][3] = __float_as_uint(As[(m0 + 8) * AS_STRIDE + kk + tq + 4]);
            }
#pragma unroll
            for (int ni = 0; ni < 4; ni++) {
                int n0 = wc * 32 + ni * 8 + tg;
                bf[ni][0] = __float_as_uint(Bs[(kk + tq) * BS_STRIDE + n0]);
                bf[ni][1] = __float_as_uint(Bs[(kk + tq + 4) * BS_STRIDE + n0]);
            }
#pragma unroll
            for (int mi = 0; mi < 4; mi++)
#pragma unroll
                for (int ni = 0; ni < 4; ni++)
                    mma_tf32(c[mi][ni], af[mi], bf[ni]);
        }
    }
#undef ISSUE

    // epilogue
#pragma unroll
    for (int mi = 0; mi < 4; mi++) {
        int r0 = blockIdx.y * 128 + wr * 64 + mi * 16 + tg;
        int r1 = r0 + 8;
#pragma unroll
        for (int ni = 0; ni < 4; ni++) {
            int cc = blockIdx.x * 128 + wc * 32 + ni * 8 + tq * 2;
            float v00 = c[mi][ni][0], v01 = c[mi][ni][1];
            float v10 = c[mi][ni][2], v11 = c[mi][ni][3];
            if (bias) {
                float b0v = bias[cc], b1v = bias[cc + 1];
                v00 += b0v; v01 += b1v; v10 += b0v; v11 += b1v;
            }
            if (EPI == 1) {
                v00 = fmaxf(v00, 0.f); v01 = fmaxf(v01, 0.f);
                v10 = fmaxf(v10, 0.f); v11 = fmaxf(v11, 0.f);
            }
            if (EPI == 2) {
                float2 e0 = *(const float2*)&res[(size_t)r0 * N + cc];
                float2 e1 = *(const float2*)&res[(size_t)r1 * N + cc];
                v00 += e0.x; v01 += e0.y; v10 += e1.x; v11 += e1.y;
            }
            if (EPI == 3) {
                int gs0 = z * M + r0, gs1 = z * M + r1;
                int i0 = sidx[gs0], i1 = sidx[gs1];
                if (i0 >= 0) {
                    float g = sgate[gs0];
                    atomicAdd(&scat[(size_t)i0 * N + cc],     g * v00);
                    atomicAdd(&scat[(size_t)i0 * N + cc + 1], g * v01);
                }
                if (i1 >= 0) {
                    float g = sgate[gs1];
                    atomicAdd(&scat[(size_t)i1 * N + cc],     g * v10);
                    atomicAdd(&scat[(size_t)i1 * N + cc + 1], g * v11);
                }
            } else {
                *(float2*)&Cout[(size_t)r0 * N + cc] = make_float2(v00, v01);
                *(float2*)&Cout[(size_t)r1 * N + cc] = make_float2(v10, v11);
            }
        }
    }
}

// ---------------- tensor-core flash attention ----------------
// Block: 128 queries x one (b,h). 8 warps, each 16 query rows x full 64 head dim.
// K/V staged in smem (stride 72 -> conflict-free for both access patterns).
__global__ __launch_bounds__(256) void attn_tc_kernel(const float* __restrict__ qkv,
                                                      float* __restrict__ aout) {
    __shared__ float Ks[64][72];
    __shared__ float Vs[64][72];
    const int bh = blockIdx.y;
    const int b = bh >> 4, h = bh & 15;
    const int tid = threadIdx.x, lane = tid & 31, w = tid >> 5;
    const int tg = lane >> 2, tq = lane & 3;
    const int q0 = blockIdx.x * 128 + w * 16;

    const float* qbase = qkv + (size_t)b * TSEQ * 3072 + h * 64;

    // Q a-fragments, scale folded in, tf32-converted, register-resident
    uint32_t qa[8][4];
    {
        const float* qr0 = qbase + (size_t)(q0 + tg) * 3072;
        const float* qr1 = qbase + (size_t)(q0 + tg + 8) * 3072;
#pragma unroll
        for (int kk = 0; kk < 8; kk++) {
            qa[kk][0] = __float_as_uint(ftf(qr0[kk * 8 + tq]     * 0.125f));
            qa[kk][1] = __float_as_uint(ftf(qr1[kk * 8 + tq]     * 0.125f));
            qa[kk][2] = __float_as_uint(ftf(qr0[kk * 8 + tq + 4] * 0.125f));
            qa[kk][3] = __float_as_uint(ftf(qr1[kk * 8 + tq + 4] * 0.125f));
        }
    }

    float oacc[8][4];
#pragma unroll
    for (int dt = 0; dt < 8; dt++)
#pragma unroll
        for (int i = 0; i < 4; i++) oacc[dt][i] = 0.f;
    float m0 = -1e30f, m1 = -1e30f, l0 = 0.f, l1 = 0.f;

    const float* kbase = qbase + 1024;
    const float* vbase = qbase + 2048;
    const int slo = (tg << 2) + (tq >> 1);
    const int shi = slo + 2;

    for (int s0 = 0; s0 < TSEQ; s0 += 64) {
        __syncthreads();
        for (int i = tid; i < 64 * 16; i += 256) {
            int j = i >> 4, dv = (i & 15) << 2;
            float4 kv = *(const float4*)(kbase + (size_t)(s0 + j) * 3072 + dv);
            float4 vv = *(const float4*)(vbase + (size_t)(s0 + j) * 3072 + dv);
            Ks[j][dv] = ftf(kv.x); Ks[j][dv + 1] = ftf(kv.y);
            Ks[j][dv + 2] = ftf(kv.z); Ks[j][dv + 3] = ftf(kv.w);
            Vs[j][dv] = ftf(vv.x); Vs[j][dv + 1] = ftf(vv.y);
            Vs[j][dv + 2] = ftf(vv.z); Vs[j][dv + 3] = ftf(vv.w);
        }
        __syncthreads();

        // S = Q * K^T  (per warp: 16 x 64)
        float s[8][4];
#pragma unroll
        for (int nt = 0; nt < 8; nt++) {
            s[nt][0] = s[nt][1] = s[nt][2] = s[nt][3] = 0.f;
#pragma unroll
            for (int kk = 0; kk < 8; kk++) {
                uint32_t bb[2] = {
                    __float_as_uint(Ks[nt * 8 + tg][kk * 8 + tq]),
                    __float_as_uint(Ks[nt * 8 + tg][kk * 8 + tq + 4])};
                mma_tf32(s[nt], qa[kk], bb);
            }
        }

        // online softmax (rows tg / tg+8, spread over lanes slo group)
        float rm0 = -1e30f, rm1 = -1e30f;
#pragma unroll
        for (int nt = 0; nt < 8; nt++) {
            rm0 = fmaxf(rm0, fmaxf(s[nt][0], s[nt][1]));
            rm1 = fmaxf(rm1, fmaxf(s[nt][2], s[nt][3]));
        }
        rm0 = fmaxf(rm0, __shfl_xor_sync(~0u, rm0, 1));
        rm0 = fmaxf(rm0, __shfl_xor_sync(~0u, rm0, 2));
        rm1 = fmaxf(rm1, __shfl_xor_sync(~0u, rm1, 1));
        rm1 = fmaxf(rm1, __shfl_xor_sync(~0u, rm1, 2));
        float mn0 = fmaxf(m0, rm0), mn1 = fmaxf(m1, rm1);
        float sc0 = __expf(m0 - mn0), sc1 = __expf(m1 - mn1);
        m0 = mn0; m1 = mn1;
        float rs0 = 0.f, rs1 = 0.f;
#pragma unroll
        for (int nt = 0; nt < 8; nt++) {
            s[nt][0] = __expf(s[nt][0] - mn0);
            s[nt][1] = __expf(s[nt][1] - mn0);
            s[nt][2] = __expf(s[nt][2] - mn1);
            s[nt][3] = __expf(s[nt][3] - mn1);
            rs0 += s[nt][0] + s[nt][1];
            rs1 += s[nt][2] + s[nt][3];
        }
        rs0 += __shfl_xor_sync(~0u, rs0, 1);
        rs0 += __shfl_xor_sync(~0u, rs0, 2);
        rs1 += __shfl_xor_sync(~0u, rs1, 1);
        rs1 += __shfl_xor_sync(~0u, rs1, 2);
        l0 = l0 * sc0 + rs0;
        l1 = l1 * sc1 + rs1;
#pragma unroll
        for (int dt = 0; dt < 8; dt++) {
            oacc[dt][0] *= sc0; oacc[dt][1] *= sc0;
            oacc[dt][2] *= sc1; oacc[dt][3] *= sc1;
        }

        // O += P * V   (P C-frag -> A-frag relayout via shuffles)
#pragma unroll
        for (int kk = 0; kk < 8; kk++) {
            uint32_t pa[4];
            float e, o;
            e = __shfl_sync(~0u, s[kk][0], slo); o = __shfl_sync(~0u, s[kk][1], slo);
            pa[0] = __float_as_uint((tq & 1) ? o : e);
            e = __shfl_sync(~0u, s[kk][2], slo); o = __shfl_sync(~0u, s[kk][3], slo);
            pa[1] = __float_as_uint((tq & 1) ? o : e);
            e = __shfl_sync(~0u, s[kk][0], shi); o = __shfl_sync(~0u, s[kk][1], shi);
            pa[2] = __float_as_uint((tq & 1) ? o : e);
            e = __shfl_sync(~0u, s[kk][2], shi); o = __shfl_sync(~0u, s[kk][3], shi);
            pa[3] = __float_as_uint((tq & 1) ? o : e);
#pragma unroll
            for (int dt = 0; dt < 8; dt++) {
                uint32_t bb[2] = {
                    __float_as_uint(Vs[kk * 8 + tq][dt * 8 + tg]),
                    __float_as_uint(Vs[kk * 8 + tq + 4][dt * 8 + tg])};
                mma_tf32(oacc[dt], pa, bb);
            }
        }
    }

    // finalize + permuted store: out[(t&31)*64+d][h*64 + (t>>5)]
    float inv0 = 1.f / l0, inv1 = 1.f / l1;
    float* ab = aout + (size_t)b * TSEQ * CDIM;
    int t0 = q0 + tg, t1 = t0 + 8;
    int c0 = h * 64 + (t0 >> 5), r0b = (t0 & 31) * 64;
    int c1 = h * 64 + (t1 >> 5), r1b = (t1 & 31) * 64;
#pragma unroll
    for (int dt = 0; dt < 8; dt++) {
        int d = dt * 8 + tq * 2;
        ab[(size_t)(r0b + d) * CDIM + c0]     = oacc[dt][0] * inv0;
        ab[(size_t)(r0b + d + 1) * CDIM + c0] = oacc[dt][1] * inv0;
        ab[(size_t)(r1b + d) * CDIM + c1]     = oacc[dt][2] * inv1;
        ab[(size_t)(r1b + d + 1) * CDIM + c1] = oacc[dt][3] * inv1;
    }
}

// ---------------- routing GEMV (warp per token) ----------------
__global__ __launch_bounds__(256) void route_kernel(const float* __restrict__ wr,
                                                    const float* __restrict__ br,
                                                    const float* __restrict__ wn,
                                                    const float* __restrict__ bn) {
    int warp = threadIdx.x >> 5, lane = threadIdx.x & 31;
    int n = blockIdx.x * 8 + warp;
    const float* hp = g_h2 + (size_t)n * CDIM;
    float pr[8], pn[8];
#pragma unroll
    for (int e = 0; e < 8; e++) { pr[e] = 0.f; pn[e] = 0.f; }
    for (int c = lane; c < CDIM; c += 32) {
        float hv = hp[c];
#pragma unroll
        for (int e = 0; e < 8; e++) {
            pr[e] += hv * wr[c * 8 + e];
            pn[e] += hv * wn[c * 8 + e];
        }
    }
#pragma unroll
    for (int e = 0; e < 8; e++) {
        for (int o = 16; o; o >>= 1) {
            pr[e] += __shfl_xor_sync(~0u, pr[e], o);
            pn[e] += __shfl_xor_sync(~0u, pn[e], o);
        }
    }
    if (lane == 0) {
#pragma unroll
        for (int e = 0; e < 8; e++) {
            g_logits[n * 8 + e]  = pr[e] + br[e];
            g_nlogits[n * 8 + e] = pn[e] + bn[e];
        }
    }
}

// ---------------- per-token routing epilogue + entropy ----------------
__global__ __launch_bounds__(256) void route_post_kernel(const float* __restrict__ noise) {
    __shared__ float red[8];
    int n = blockIdx.x * blockDim.x + threadIdx.x;
    float noisy[8];
    float mx = -1e30f;
#pragma unroll
    for (int e = 0; e < 8; e++) {
        float nl = g_nlogits[n * 8 + e];
        float sp = log1pf(expf(-fabsf(nl))) + fmaxf(nl, 0.f);   // softplus
        float v = g_logits[n * 8 + e] + noise[n * 8 + e] * sp;
        noisy[e] = v;
        mx = fmaxf(mx, v);
    }
    float s = 0.f, p[8];
#pragma unroll
    for (int e = 0; e < 8; e++) { p[e] = expf(noisy[e] - mx); s += p[e]; }
    float inv = 1.f / s, ent = 0.f;
#pragma unroll
    for (int e = 0; e < 8; e++) { float pe = p[e] * inv; ent -= pe * logf(pe + 1e-8f); }

    int i0 = 0;
#pragma unroll
    for (int e = 1; e < 8; e++) if (noisy[e] > noisy[i0]) i0 = e;
    int i1 = (i0 == 0) ? 1 : 0;
#pragma unroll
    for (int e = 0; e < 8; e++) if (e != i0 && noisy[e] > noisy[i1]) i1 = e;
    float dgl = expf(noisy[i1] - noisy[i0]);
    float g0 = 1.f / (1.f + dgl);
    float g1 = dgl * g0;
    g_sel[n] = i0 | (i1 << 8);
    g_gate[2 * n] = g0;
    g_gate[2 * n + 1] = g1;

    float es = ent;
    for (int o = 16; o; o >>= 1) es += __shfl_xor_sync(~0u, es, o);
    int lane = threadIdx.x & 31, wid = threadIdx.x >> 5;
    if (lane == 0) red[wid] = es;
    __syncthreads();
    if (threadIdx.x < 8) {
        float t = red[threadIdx.x];
        for (int o = 4; o; o >>= 1) t += __shfl_xor_sync(0xffu, t, o);
        if (threadIdx.x == 0) atomicAdd(&g_ent, t);
    }
}

// ---------------- ordered capacity assignment (1 warp, ballot scan) ----------------
__global__ void assign_kernel() {
    int lane = threadIdx.x;
    int cnt[8];
#pragma unroll
    for (int e = 0; e < 8; e++) cnt[e] = 0;
    unsigned lt = (1u << lane) - 1u;
    for (int n0 = 0; n0 < NTOK; n0 += 32) {
        int n = n0 + lane;
        int sel = g_sel[n];
        int e0 = sel & 255, e1 = (sel >> 8) & 255;
        float g0 = g_gate[2 * n], g1 = g_gate[2 * n + 1];
#pragma unroll
        for (int e = 0; e < 8; e++) {
            bool mt = (e0 == e) || (e1 == e);
            unsigned mask = __ballot_sync(~0u, mt);
            if (mt) {
                int r = cnt[e] + __popc(mask & lt);
                if (r < CAP) {
                    g_slot_idx[e * CAP + r]  = n;
                    g_slot_gate[e * CAP + r] = (e0 == e) ? g0 : g1;
                }
            }
            cnt[e] += __popc(mask);
        }
    }
#pragma unroll
    for (int e = 0; e < 8; e++) {
        for (int r = cnt[e] + lane; r < CAP; r += 32) {
            g_slot_idx[e * CAP + r]  = -1;
            g_slot_gate[e * CAP + r] = 0.f;
        }
    }
}

// ---------------- final: out = x2 + updates ; tail = entropy/N ----------------
__global__ void final_kernel(float* __restrict__ out, int out_size) {
    int i = blockIdx.x * blockDim.x + threadIdx.x;
    if (i < NTOK * CDIM) out[i] = g_x2[i] + g_upd[i];
    else if (i < out_size) out[i] = g_ent * (1.f / NTOK);
}

// ---------------- host launcher ----------------
static float* symf(const void* s) { void* p = nullptr; cudaGetSymbolAddress(&p, s); return (float*)p; }
static int*   symi(const void* s) { void* p = nullptr; cudaGetSymbolAddress(&p, s); return (int*)p; }

extern "C" void kernel_launch(void* const* d_in, const int* in_sizes, int n_in,
                              void* d_out, int out_size) {
    const float* x       = (const float*)d_in[0];
    const float* noise   = (const float*)d_in[1];
    const float* gamma1  = (const float*)d_in[2];
    const float* beta1   = (const float*)d_in[3];
    const float* gamma2  = (const float*)d_in[4];
    const float* beta2   = (const float*)d_in[5];
    const float* w_qkv   = (const float*)d_in[6];
    const float* w_out   = (const float*)d_in[7];
    const float* w_route = (const float*)d_in[8];
    const float* b_route = (const float*)d_in[9];
    const float* w_noise = (const float*)d_in[10];
    const float* b_noise = (const float*)d_in[11];
    const float* w1      = (const float*)d_in[12];
    const float* b1      = (const float*)d_in[13];
    const float* w2      = (const float*)d_in[14];
    const float* b2      = (const float*)d_in[15];
    float* out = (float*)d_out;

    float* p_h1   = symf(g_h1);
    float* p_qkv  = symf(g_qkv);
    float* p_attn = symf(g_attn);
    float* p_x2   = symf(g_x2);
    float* p_h2   = symf(g_h2);
    float* p_hid  = symf(g_hid);
    float* p_upd  = symf(g_upd);
    float* p_zero = symf(g_zero);
    int*   p_sidx = symi(g_slot_idx);
    float* p_sg   = symf(g_slot_gate);

    static int smem_set = 0;
    if (!smem_set) {
        cudaFuncSetAttribute(tgemm2_kernel<0, false>, cudaFuncAttributeMaxDynamicSharedMemorySize, SMEM_BYTES);
        cudaFuncSetAttribute(tgemm2_kernel<2, false>, cudaFuncAttributeMaxDynamicSharedMemorySize, SMEM_BYTES);
        cudaFuncSetAttribute(tgemm2_kernel<1, true>,  cudaFuncAttributeMaxDynamicSharedMemorySize, SMEM_BYTES);
        cudaFuncSetAttribute(tgemm2_kernel<3, false>, cudaFuncAttributeMaxDynamicSharedMemorySize, SMEM_BYTES);
        smem_set = 1;
    }

    // 0) zero updates + zero-row + entropy
    zero_kernel<<<NTOK * CDIM / 4 / 256, 256>>>();
    // 1) ln1
    ln_kernel<<<NTOK, 256>>>(x, gamma1, beta1, p_h1);
    // 2) qkv = h1 @ w_qkv  [4096 x 3072 x 1024]
    tgemm2_kernel<0, false><<<dim3(3072 / 128, 4096 / 128, 1), 256, SMEM_BYTES>>>(
        p_h1, w_qkv, p_qkv, 4096, 3072, 1024,
        nullptr, nullptr, nullptr, nullptr, nullptr, p_zero, 0, 0, 0, 0);
    // 3) tensor-core flash attention -> permuted activation
    attn_tc_kernel<<<dim3(TSEQ / 128, BSZ * NHEADS), 256>>>(p_qkv, p_attn);
    // 4) x2 = x + attn @ w_out  [4096 x 1024 x 1024]
    tgemm2_kernel<2, false><<<dim3(1024 / 128, 4096 / 128, 1), 256, SMEM_BYTES>>>(
        p_attn, w_out, p_x2, 4096, 1024, 1024,
        nullptr, x, nullptr, nullptr, nullptr, p_zero, 0, 0, 0, 0);
    // 5) ln2
    ln_kernel<<<NTOK, 256>>>(p_x2, gamma2, beta2, p_h2);
    // 6) routing GEMV
    route_kernel<<<NTOK / 8, 256>>>(w_route, b_route, w_noise, b_noise);
    // 7) routing epilogue (noisy top-2, gates, entropy)
    route_post_kernel<<<NTOK / 256, 256>>>(noise);
    // 8) ordered capacity assignment
    assign_kernel<<<1, 32>>>();
    // 9) hid = relu(h2[slot] @ w1 + b1)  per expert [1024 x 4096 x 1024], fused gather
    tgemm2_kernel<1, true><<<dim3(4096 / 128, 1024 / 128, NEXP), 256, SMEM_BYTES>>>(
        p_h2, w1, p_hid, 1024, 4096, 1024,
        b1, nullptr, p_sidx, nullptr, nullptr, p_zero,
        0, (size_t)CDIM * DFF, (size_t)CAP * DFF, DFF);
    // 10) yo = hid @ w2 + b2, gated atomic scatter into updates [1024 x 1024 x 4096]
    tgemm2_kernel<3, false><<<dim3(1024 / 128, 1024 / 128, NEXP), 256, SMEM_BYTES>>>(
        p_hid, w2, nullptr, 1024, 1024, 4096,
        b2, nullptr, p_sidx, p_sg, p_upd, p_zero,
        (size_t)CAP * DFF, (size_t)DFF * CDIM, 0, CDIM);
    // 11) final add + entropy tail
    final_kernel<<<(out_size + 255) / 256, 256>>>(out, out_size);
}